// round 4
// baseline (speedup 1.0000x reference)
#include <cuda_runtime.h>

#define BB 16384
#define TT 64
typedef unsigned long long u64;

// Ping-pong layer buffers: [B][T][64] (fwd in [0:32), bwd in [32:64))
__device__ float g_buf0[BB * TT * 64];
__device__ float g_buf1[BB * TT * 64];
// Input-gate pre-activations for the current layer: [B][T][192]
// col g = dir*96 + (gate*32 + j), includes bih.
__device__ float g_xg[(size_t)BB * TT * 192];

__device__ __forceinline__ float sigf(float x) {
    return __fdividef(1.0f, 1.0f + __expf(-x));
}
__device__ __forceinline__ float tanh_fast(float x) {
    float e = __expf(-2.0f * x);
    return __fdividef(1.0f - e, 1.0f + e);
}

// Packed f32x2 FMA (2 MACs/instr; ptxas never emits this from C++).
__device__ __forceinline__ u64 fma2(u64 a, u64 b, u64 c) {
    u64 d;
    asm("fma.rn.f32x2 %0, %1, %2, %3;" : "=l"(d) : "l"(a), "l"(b), "l"(c));
    return d;
}
__device__ __forceinline__ u64 splat2(float x) {
    u64 d;
    asm("mov.b64 %0, {%1, %1};" : "=l"(d) : "f"(x));
    return d;
}
__device__ __forceinline__ float2 unpk(u64 v) {
    float2 r;
    asm("mov.b64 {%0, %1}, %2;" : "=f"(r.x), "=f"(r.y) : "l"(v));
    return r;
}

// ---------------------------------------------------------------------------
// Layer 0: input K=2. One warp per (batch, dir). Lane j owns hidden unit j,
// computes all 3 gates. Whh rows in registers; x staged in smem once;
// h broadcast via smem double buffer, one __syncwarp per step.
// ---------------------------------------------------------------------------
__global__ __launch_bounds__(128) void gru_l0(
    const float* __restrict__ x,
    const float* __restrict__ Wih0, const float* __restrict__ Whh0,
    const float* __restrict__ bih0, const float* __restrict__ bhh0)
{
    const int w = threadIdx.x >> 5, lane = threadIdx.x & 31;
    const int b = blockIdx.x * 4 + w;
    const int dir = blockIdx.y;

    __shared__ __align__(16) float hb[4][2][32];
    __shared__ __align__(16) float xs[4][128];   // whole input sequence per warp

    const float* wi = Wih0 + dir * 96 * 2;
    const float* wh = Whh0 + dir * 96 * 32;
    const float* bi = bih0 + dir * 96;
    const float* bh = bhh0 + dir * 96;

    {
        float4 v = *(const float4*)(x + (size_t)b * 128 + lane * 4);
        *(float4*)&xs[w][lane * 4] = v;
    }

    const float wx0 = wi[(lane) * 2 + 0],      wx1 = wi[(lane) * 2 + 1];
    const float wz0 = wi[(32 + lane) * 2 + 0], wz1 = wi[(32 + lane) * 2 + 1];
    const float wn0 = wi[(64 + lane) * 2 + 0], wn1 = wi[(64 + lane) * 2 + 1];

    float whr[32], whz[32], whn[32];
#pragma unroll
    for (int k = 0; k < 32; k += 4) {
        float4 a = *(const float4*)&wh[(lane) * 32 + k];
        whr[k] = a.x; whr[k + 1] = a.y; whr[k + 2] = a.z; whr[k + 3] = a.w;
        float4 c = *(const float4*)&wh[(32 + lane) * 32 + k];
        whz[k] = c.x; whz[k + 1] = c.y; whz[k + 2] = c.z; whz[k + 3] = c.w;
        float4 d = *(const float4*)&wh[(64 + lane) * 32 + k];
        whn[k] = d.x; whn[k + 1] = d.y; whn[k + 2] = d.z; whn[k + 3] = d.w;
    }
    const float br  = bi[lane] + bh[lane];
    const float bz  = bi[32 + lane] + bh[32 + lane];
    const float bxn = bi[64 + lane];
    const float bhn = bh[64 + lane];

    float h = 0.0f;
    hb[w][0][lane] = 0.0f;
    __syncwarp();

    float* outp = g_buf0 + (size_t)b * TT * 64 + dir * 32 + lane;

    for (int t = 0; t < TT; t++) {
        const int te = dir ? (TT - 1 - t) : t;
        const float x0 = xs[w][te * 2 + 0];
        const float x1 = xs[w][te * 2 + 1];

        float sr0 = fmaf(x1, wx1, fmaf(x0, wx0, br)),  sr1 = 0.f;
        float sz0 = fmaf(x1, wz1, fmaf(x0, wz0, bz)),  sz1 = 0.f;
        float sn0 = bhn, sn1 = 0.f;

        const float4* h4 = (const float4*)hb[w][t & 1];
#pragma unroll
        for (int c = 0; c < 8; c++) {
            float4 v = h4[c];
            sr0 = fmaf(v.x, whr[4 * c + 0], sr0);
            sr0 = fmaf(v.y, whr[4 * c + 1], sr0);
            sr1 = fmaf(v.z, whr[4 * c + 2], sr1);
            sr1 = fmaf(v.w, whr[4 * c + 3], sr1);
            sz0 = fmaf(v.x, whz[4 * c + 0], sz0);
            sz0 = fmaf(v.y, whz[4 * c + 1], sz0);
            sz1 = fmaf(v.z, whz[4 * c + 2], sz1);
            sz1 = fmaf(v.w, whz[4 * c + 3], sz1);
            sn0 = fmaf(v.x, whn[4 * c + 0], sn0);
            sn0 = fmaf(v.y, whn[4 * c + 1], sn0);
            sn1 = fmaf(v.z, whn[4 * c + 2], sn1);
            sn1 = fmaf(v.w, whn[4 * c + 3], sn1);
        }
        const float r = sigf(sr0 + sr1);
        const float z = sigf(sz0 + sz1);
        const float n = tanh_fast(fmaf(r, sn0 + sn1, fmaf(x1, wn1, fmaf(x0, wn0, bxn))));
        h = fmaf(z, h - n, n);

        hb[w][(t + 1) & 1][lane] = h;
        outp[(size_t)te * 64] = h;
        __syncwarp();
    }
}

// ---------------------------------------------------------------------------
// Input GEMM for layers 1/2 (FFMA2 version):
//   xg[m][g] = sum_k in[m][k] * W[g][k] + bih[g],  m < B*T, g < 192, K = 64.
// Block: 256 thr, tile M=64 x N=96 (grid.y = dir half). Accumulators paired
// along N (c,c+1) as f32x2; X staged in smem PRE-SPLAT (x,x) as u64, k-chunked
// (2 x 32) to fit static smem. W pairs come free from contiguous Ws columns.
// Thread (tx=tid&15, ty=tid>>4): rows r0=4*ty..+3, cols c0=6*tx..+5.
// Per k: 2x LDS.128 (splat X) + 3x LDS.64 (W pairs) + 12 FFMA2.
// ---------------------------------------------------------------------------
__global__ __launch_bounds__(256) void xgemm(
    int srcbuf,
    const float* __restrict__ W,     // [192][64] for this layer
    const float* __restrict__ bias)  // [192]
{
    const float* in = srcbuf ? g_buf1 : g_buf0;

    __shared__ __align__(16) u64  Xs2[32][66];   // [k][m] splat pairs (+pad)
    __shared__ __align__(16) float Ws[64][100];  // [k][c], c < 96 (+pad)
    __shared__ float Bs[96];

    const int tid = threadIdx.x;
    const size_t m0 = (size_t)blockIdx.x * 64;
    const int c0g = blockIdx.y * 96;

    // Load W half transposed: W[c0g+g][k] -> Ws[k][g]
    for (int q = tid; q < 96 * 16; q += 256) {
        const int g = q >> 4, k4 = (q & 15) << 2;
        float4 v = *(const float4*)&W[(size_t)(c0g + g) * 64 + k4];
        Ws[k4 + 0][g] = v.x; Ws[k4 + 1][g] = v.y;
        Ws[k4 + 2][g] = v.z; Ws[k4 + 3][g] = v.w;
    }
    if (tid < 96) Bs[tid] = bias[c0g + tid];

    const int tx = tid & 15, ty = tid >> 4;
    const int r0 = ty * 4, c0 = tx * 6;

    u64 acc[4][3];
#pragma unroll
    for (int i = 0; i < 4; i++)
#pragma unroll
        for (int j = 0; j < 3; j++) acc[i][j] = 0ull;

#pragma unroll
    for (int chunk = 0; chunk < 2; chunk++) {
        const int kb = chunk * 32;
        // Stage X k-chunk splat: in[m0+r][kb+k] -> Xs2[k][r] = (x,x)
        __syncthreads();
        for (int q = tid; q < 512; q += 256) {
            const int r = q >> 3, k4 = (q & 7) << 2;
            float4 v = *(const float4*)&in[(m0 + r) * 64 + kb + k4];
            Xs2[k4 + 0][r] = splat2(v.x);
            Xs2[k4 + 1][r] = splat2(v.y);
            Xs2[k4 + 2][r] = splat2(v.z);
            Xs2[k4 + 3][r] = splat2(v.w);
        }
        __syncthreads();

#pragma unroll
        for (int k = 0; k < 32; k++) {
            ulonglong2 xa = *(const ulonglong2*)&Xs2[k][r0];
            ulonglong2 xb = *(const ulonglong2*)&Xs2[k][r0 + 2];
            const u64 w0 = *(const u64*)&Ws[kb + k][c0 + 0];
            const u64 w1 = *(const u64*)&Ws[kb + k][c0 + 2];
            const u64 w2 = *(const u64*)&Ws[kb + k][c0 + 4];
            acc[0][0] = fma2(xa.x, w0, acc[0][0]);
            acc[0][1] = fma2(xa.x, w1, acc[0][1]);
            acc[0][2] = fma2(xa.x, w2, acc[0][2]);
            acc[1][0] = fma2(xa.y, w0, acc[1][0]);
            acc[1][1] = fma2(xa.y, w1, acc[1][1]);
            acc[1][2] = fma2(xa.y, w2, acc[1][2]);
            acc[2][0] = fma2(xb.x, w0, acc[2][0]);
            acc[2][1] = fma2(xb.x, w1, acc[2][1]);
            acc[2][2] = fma2(xb.x, w2, acc[2][2]);
            acc[3][0] = fma2(xb.y, w0, acc[3][0]);
            acc[3][1] = fma2(xb.y, w1, acc[3][1]);
            acc[3][2] = fma2(xb.y, w2, acc[3][2]);
        }
    }

    // Epilogue: add bias, store.
    float bv[6];
#pragma unroll
    for (int j = 0; j < 6; j++) bv[j] = Bs[c0 + j];
#pragma unroll
    for (int i = 0; i < 4; i++) {
        float* o = g_xg + (m0 + r0 + i) * 192 + c0g + c0;
#pragma unroll
        for (int j = 0; j < 3; j++) {
            float2 p = unpk(acc[i][j]);
            p.x += bv[2 * j];
            p.y += bv[2 * j + 1];
            *(float2*)&o[2 * j] = p;
        }
    }
}

// ---------------------------------------------------------------------------
// Recurrence for layers 1/2. One warp per (batch, dir); lane j owns unit j,
// all 3 gates (96 weight regs, 96 FFMA/step). xg read with distance-4
// register-ring prefetch. No block barriers.
// ---------------------------------------------------------------------------
__global__ __launch_bounds__(128) void gru_rec(
    int dstbuf,
    const float* __restrict__ Whh,   // [2][96][32] for this layer
    const float* __restrict__ bhh)   // [192]
{
    float* out = dstbuf ? g_buf1 : g_buf0;

    const int w = threadIdx.x >> 5, lane = threadIdx.x & 31;
    const int b = blockIdx.x * 4 + w;
    const int dir = blockIdx.y;

    __shared__ __align__(16) float hb[4][2][32];

    const float* wh = Whh + dir * 96 * 32;
    const float* bh = bhh + dir * 96;

    float whr[32], whz[32], whn[32];
#pragma unroll
    for (int k = 0; k < 32; k += 4) {
        float4 a = *(const float4*)&wh[(lane) * 32 + k];
        whr[k] = a.x; whr[k + 1] = a.y; whr[k + 2] = a.z; whr[k + 3] = a.w;
        float4 c = *(const float4*)&wh[(32 + lane) * 32 + k];
        whz[k] = c.x; whz[k + 1] = c.y; whz[k + 2] = c.z; whz[k + 3] = c.w;
        float4 d = *(const float4*)&wh[(64 + lane) * 32 + k];
        whn[k] = d.x; whn[k + 1] = d.y; whn[k + 2] = d.z; whn[k + 3] = d.w;
    }
    const float br = bh[lane];
    const float bz = bh[32 + lane];
    const float bn = bh[64 + lane];

    const float* xgb = g_xg + (size_t)b * TT * 192 + dir * 96 + lane;
    float* outb = out + (size_t)b * TT * 64 + dir * 32 + lane;
    const int sd = dir ? -1 : 1;
    int te = dir ? (TT - 1) : 0;

    // Prefetch ring, distance 4.
    float pxr[4], pxz[4], pxn[4];
#pragma unroll
    for (int u = 0; u < 4; u++) {
        const float* p = xgb + (size_t)(te + sd * u) * 192;
        pxr[u] = p[0]; pxz[u] = p[32]; pxn[u] = p[64];
    }

    float h = 0.0f;
    hb[w][0][lane] = 0.0f;
    __syncwarp();

    for (int tb = 0; tb < TT; tb += 4) {
#pragma unroll
        for (int u = 0; u < 4; u++) {
            const int t = tb + u;
            const int tp = (t + 4 < TT) ? (te + sd * 4) : te;
            const float* p = xgb + (size_t)tp * 192;
            const float fr = p[0], fz = p[32], fn = p[64];

            float sr0 = pxr[u] + br, sr1 = 0.f;
            float sz0 = pxz[u] + bz, sz1 = 0.f;
            float sn0 = bn, sn1 = 0.f;

            const float4* h4 = (const float4*)hb[w][t & 1];
#pragma unroll
            for (int c = 0; c < 8; c++) {
                float4 v = h4[c];
                sr0 = fmaf(v.x, whr[4 * c + 0], sr0);
                sr0 = fmaf(v.y, whr[4 * c + 1], sr0);
                sr1 = fmaf(v.z, whr[4 * c + 2], sr1);
                sr1 = fmaf(v.w, whr[4 * c + 3], sr1);
                sz0 = fmaf(v.x, whz[4 * c + 0], sz0);
                sz0 = fmaf(v.y, whz[4 * c + 1], sz0);
                sz1 = fmaf(v.z, whz[4 * c + 2], sz1);
                sz1 = fmaf(v.w, whz[4 * c + 3], sz1);
                sn0 = fmaf(v.x, whn[4 * c + 0], sn0);
                sn0 = fmaf(v.y, whn[4 * c + 1], sn0);
                sn1 = fmaf(v.z, whn[4 * c + 2], sn1);
                sn1 = fmaf(v.w, whn[4 * c + 3], sn1);
            }
            const float r = sigf(sr0 + sr1);
            const float z = sigf(sz0 + sz1);
            const float n = tanh_fast(fmaf(r, sn0 + sn1, pxn[u]));
            h = fmaf(z, h - n, n);

            hb[w][(t + 1) & 1][lane] = h;
            outb[(size_t)te * 64] = h;
            pxr[u] = fr; pxz[u] = fz; pxn[u] = fn;
            te += sd;
            __syncwarp();
        }
    }
}

// ---------------------------------------------------------------------------
// Final FC: y = tanh(out @ Wfc.T + bfc). Warp per row, shuffle reduction.
// ---------------------------------------------------------------------------
__global__ __launch_bounds__(256) void fc_kernel(
    const float* __restrict__ Wfc, const float* __restrict__ bfc,
    float* __restrict__ outp)
{
    const float* in = g_buf0;  // layer 2 output
    const int lane = threadIdx.x & 31;
    const int warp = (blockIdx.x * blockDim.x + threadIdx.x) >> 5;
    const int nwarps = (gridDim.x * blockDim.x) >> 5;

    const float w0a = __ldg(&Wfc[2 * lane]),      w0b = __ldg(&Wfc[2 * lane + 1]);
    const float w1a = __ldg(&Wfc[64 + 2 * lane]), w1b = __ldg(&Wfc[64 + 2 * lane + 1]);
    const float b0 = __ldg(&bfc[0]), b1 = __ldg(&bfc[1]);

    const int nrows = BB * TT;
    for (int row = warp; row < nrows; row += nwarps) {
        float2 xv = *(const float2*)&in[(size_t)row * 64 + 2 * lane];
        float y0 = fmaf(xv.y, w0b, xv.x * w0a);
        float y1 = fmaf(xv.y, w1b, xv.x * w1a);
#pragma unroll
        for (int o = 16; o > 0; o >>= 1) {
            y0 += __shfl_xor_sync(0xFFFFFFFFu, y0, o);
            y1 += __shfl_xor_sync(0xFFFFFFFFu, y1, o);
        }
        if (lane == 0) {
            float2 r;
            r.x = tanh_fast(y0 + b0);
            r.y = tanh_fast(y1 + b1);
            *(float2*)&outp[(size_t)row * 2] = r;
        }
    }
}

// ---------------------------------------------------------------------------
extern "C" void kernel_launch(void* const* d_in, const int* in_sizes, int n_in,
                              void* d_out, int out_size)
{
    const float* x    = (const float*)d_in[0];
    const float* Wih0 = (const float*)d_in[1];
    const float* Whh0 = (const float*)d_in[2];
    const float* bih0 = (const float*)d_in[3];
    const float* bhh0 = (const float*)d_in[4];
    const float* Wih  = (const float*)d_in[5];
    const float* Whh  = (const float*)d_in[6];
    const float* bih  = (const float*)d_in[7];
    const float* bhh  = (const float*)d_in[8];
    const float* Wfc  = (const float*)d_in[9];
    const float* bfc  = (const float*)d_in[10];
    float* out = (float*)d_out;

    const int MB = (BB * TT) / 64;  // xgemm grid.x

    // Layer 0 -> buf0
    gru_l0<<<dim3(BB / 4, 2), 128>>>(x, Wih0, Whh0, bih0, bhh0);
    // Layer 1: buf0 -> xg -> buf1
    xgemm<<<dim3(MB, 2), 256>>>(0, Wih, bih);
    gru_rec<<<dim3(BB / 4, 2), 128>>>(1, Whh, bhh);
    // Layer 2: buf1 -> xg -> buf0
    xgemm<<<dim3(MB, 2), 256>>>(1, Wih + 192 * 64, bih + 192);
    gru_rec<<<dim3(BB / 4, 2), 128>>>(0, Whh + 192 * 32, bhh + 192);
    // FC
    fc_kernel<<<2048, 256>>>(Wfc, bfc, out);
}

// round 5
// speedup vs baseline: 1.1674x; 1.1674x over previous
#include <cuda_runtime.h>

#define BB 16384
#define TT 64

// Ping-pong layer buffers: [B][T][64] (fwd in [0:32), bwd in [32:64))
__device__ float g_buf0[BB * TT * 64];
__device__ float g_buf1[BB * TT * 64];
// Input-gate pre-activations for the current layer: [B][T][192]
// col g = dir*96 + (gate*32 + j), includes bih.
__device__ float g_xg[(size_t)BB * TT * 192];

__device__ __forceinline__ float sigf(float x) {
    return __fdividef(1.0f, 1.0f + __expf(-x));
}
__device__ __forceinline__ float tanh_fast(float x) {
    float e = __expf(-2.0f * x);
    return __fdividef(1.0f - e, 1.0f + e);
}

// ---------------------------------------------------------------------------
// Layer 0: input K=2. One warp per (batch, dir). Lane j owns hidden unit j,
// computes all 3 gates. Whh rows in registers; x staged in smem once;
// h broadcast via smem double buffer, one __syncwarp per step.
// ---------------------------------------------------------------------------
__global__ __launch_bounds__(128) void gru_l0(
    const float* __restrict__ x,
    const float* __restrict__ Wih0, const float* __restrict__ Whh0,
    const float* __restrict__ bih0, const float* __restrict__ bhh0)
{
    const int w = threadIdx.x >> 5, lane = threadIdx.x & 31;
    const int b = blockIdx.x * 4 + w;
    const int dir = blockIdx.y;

    __shared__ __align__(16) float hb[4][2][32];
    __shared__ __align__(16) float xs[4][128];   // whole input sequence per warp

    const float* wi = Wih0 + dir * 96 * 2;
    const float* wh = Whh0 + dir * 96 * 32;
    const float* bi = bih0 + dir * 96;
    const float* bh = bhh0 + dir * 96;

    {
        float4 v = *(const float4*)(x + (size_t)b * 128 + lane * 4);
        *(float4*)&xs[w][lane * 4] = v;
    }

    const float wx0 = wi[(lane) * 2 + 0],      wx1 = wi[(lane) * 2 + 1];
    const float wz0 = wi[(32 + lane) * 2 + 0], wz1 = wi[(32 + lane) * 2 + 1];
    const float wn0 = wi[(64 + lane) * 2 + 0], wn1 = wi[(64 + lane) * 2 + 1];

    float whr[32], whz[32], whn[32];
#pragma unroll
    for (int k = 0; k < 32; k += 4) {
        float4 a = *(const float4*)&wh[(lane) * 32 + k];
        whr[k] = a.x; whr[k + 1] = a.y; whr[k + 2] = a.z; whr[k + 3] = a.w;
        float4 c = *(const float4*)&wh[(32 + lane) * 32 + k];
        whz[k] = c.x; whz[k + 1] = c.y; whz[k + 2] = c.z; whz[k + 3] = c.w;
        float4 d = *(const float4*)&wh[(64 + lane) * 32 + k];
        whn[k] = d.x; whn[k + 1] = d.y; whn[k + 2] = d.z; whn[k + 3] = d.w;
    }
    const float br  = bi[lane] + bh[lane];
    const float bz  = bi[32 + lane] + bh[32 + lane];
    const float bxn = bi[64 + lane];
    const float bhn = bh[64 + lane];

    float h = 0.0f;
    hb[w][0][lane] = 0.0f;
    __syncwarp();

    float* outp = g_buf0 + (size_t)b * TT * 64 + dir * 32 + lane;

    for (int t = 0; t < TT; t++) {
        const int te = dir ? (TT - 1 - t) : t;
        const float x0 = xs[w][te * 2 + 0];
        const float x1 = xs[w][te * 2 + 1];

        float sr0 = fmaf(x1, wx1, fmaf(x0, wx0, br)),  sr1 = 0.f;
        float sz0 = fmaf(x1, wz1, fmaf(x0, wz0, bz)),  sz1 = 0.f;
        float sn0 = bhn, sn1 = 0.f;

        const float4* h4 = (const float4*)hb[w][t & 1];
#pragma unroll
        for (int c = 0; c < 8; c++) {
            float4 v = h4[c];
            sr0 = fmaf(v.x, whr[4 * c + 0], sr0);
            sr0 = fmaf(v.y, whr[4 * c + 1], sr0);
            sr1 = fmaf(v.z, whr[4 * c + 2], sr1);
            sr1 = fmaf(v.w, whr[4 * c + 3], sr1);
            sz0 = fmaf(v.x, whz[4 * c + 0], sz0);
            sz0 = fmaf(v.y, whz[4 * c + 1], sz0);
            sz1 = fmaf(v.z, whz[4 * c + 2], sz1);
            sz1 = fmaf(v.w, whz[4 * c + 3], sz1);
            sn0 = fmaf(v.x, whn[4 * c + 0], sn0);
            sn0 = fmaf(v.y, whn[4 * c + 1], sn0);
            sn1 = fmaf(v.z, whn[4 * c + 2], sn1);
            sn1 = fmaf(v.w, whn[4 * c + 3], sn1);
        }
        const float r = sigf(sr0 + sr1);
        const float z = sigf(sz0 + sz1);
        const float n = tanh_fast(fmaf(r, sn0 + sn1, fmaf(x1, wn1, fmaf(x0, wn0, bxn))));
        h = fmaf(z, h - n, n);

        hb[w][(t + 1) & 1][lane] = h;
        outp[(size_t)te * 64] = h;
        __syncwarp();
    }
}

// ---------------------------------------------------------------------------
// Input GEMM for layers 1/2:
//   xg[m][g] = sum_k in[m][k] * W[g][k] + bih[g],  m < B*T, g < 192, K = 64.
// Block: 256 thr, tile M=64 x N=96 (grid.y = dir half).
// X in NATURAL layout Xs[m][k] (straight float4 copy in, float4 reads out);
// W transposed Ws[k][c]. Inner loop blocked by 4 k's:
//   per thread per 4k: 4x LDS.128 (X rows, warp-broadcast) + 12x LDS.64 (W)
//   + 96 FMA  (vs 16x LDS.32 + 12x LDS.64 before — 43% fewer LDS instrs).
// Thread (tx=tid&15, ty=tid>>4): rows ty+16i, cols tx*6..tx*6+5.
// ---------------------------------------------------------------------------
__global__ __launch_bounds__(256) void xgemm(
    int srcbuf,
    const float* __restrict__ W,     // [192][64] for this layer
    const float* __restrict__ bias)  // [192]
{
    const float* in = srcbuf ? g_buf1 : g_buf0;

    __shared__ __align__(16) float Xs[64][68];   // [m][k] natural (+pad, 16B-aligned rows)
    __shared__ __align__(16) float Ws[64][100];  // [k][c], c < 96 (+pad)
    __shared__ float Bs[96];

    const int tid = threadIdx.x;
    const size_t m0 = (size_t)blockIdx.x * 64;
    const int c0g = blockIdx.y * 96;

    // Load W half transposed: W[c0g+g][k] -> Ws[k][g]
    for (int q = tid; q < 96 * 16; q += 256) {
        const int g = q >> 4, k4 = (q & 15) << 2;
        float4 v = *(const float4*)&W[(size_t)(c0g + g) * 64 + k4];
        Ws[k4 + 0][g] = v.x; Ws[k4 + 1][g] = v.y;
        Ws[k4 + 2][g] = v.z; Ws[k4 + 3][g] = v.w;
    }
    if (tid < 96) Bs[tid] = bias[c0g + tid];

    // Load X tile natural: in[m0+r][k] -> Xs[r][k]  (no transpose)
    for (int q = tid; q < 64 * 16; q += 256) {
        const int r = q >> 4, k4 = (q & 15) << 2;
        *(float4*)&Xs[r][k4] = *(const float4*)&in[(m0 + r) * 64 + k4];
    }
    __syncthreads();

    const int tx = tid & 15, ty = tid >> 4;
    const int c0 = tx * 6;
    float acc[4][6];
#pragma unroll
    for (int i = 0; i < 4; i++)
#pragma unroll
        for (int j = 0; j < 6; j++) acc[i][j] = 0.0f;

#pragma unroll 4
    for (int k0 = 0; k0 < 64; k0 += 4) {
        float4 xv[4];
#pragma unroll
        for (int i = 0; i < 4; i++)
            xv[i] = *(const float4*)&Xs[ty + 16 * i][k0];
#pragma unroll
        for (int kk = 0; kk < 4; kk++) {
            const int k = k0 + kk;
            float2 w0 = *(const float2*)&Ws[k][c0 + 0];
            float2 w1 = *(const float2*)&Ws[k][c0 + 2];
            float2 w2 = *(const float2*)&Ws[k][c0 + 4];
#pragma unroll
            for (int i = 0; i < 4; i++) {
                const float xi = (kk == 0) ? xv[i].x : (kk == 1) ? xv[i].y
                               : (kk == 2) ? xv[i].z : xv[i].w;
                acc[i][0] = fmaf(xi, w0.x, acc[i][0]);
                acc[i][1] = fmaf(xi, w0.y, acc[i][1]);
                acc[i][2] = fmaf(xi, w1.x, acc[i][2]);
                acc[i][3] = fmaf(xi, w1.y, acc[i][3]);
                acc[i][4] = fmaf(xi, w2.x, acc[i][4]);
                acc[i][5] = fmaf(xi, w2.y, acc[i][5]);
            }
        }
    }

    // Epilogue: add bias, store.
    float bv[6];
#pragma unroll
    for (int j = 0; j < 6; j++) bv[j] = Bs[c0 + j];
#pragma unroll
    for (int i = 0; i < 4; i++) {
        float* o = g_xg + (m0 + ty + 16 * i) * 192 + c0g + c0;
#pragma unroll
        for (int j = 0; j < 6; j += 2) {
            float2 v;
            v.x = acc[i][j] + bv[j];
            v.y = acc[i][j + 1] + bv[j + 1];
            *(float2*)&o[j] = v;
        }
    }
}

// ---------------------------------------------------------------------------
// Recurrence for layers 1/2. One warp per (batch, dir); lane j owns unit j,
// all 3 gates (96 weight regs, 96 FFMA/step). xg read with distance-4
// register-ring prefetch. No block barriers.
// ---------------------------------------------------------------------------
__global__ __launch_bounds__(128) void gru_rec(
    int dstbuf,
    const float* __restrict__ Whh,   // [2][96][32] for this layer
    const float* __restrict__ bhh)   // [192]
{
    float* out = dstbuf ? g_buf1 : g_buf0;

    const int w = threadIdx.x >> 5, lane = threadIdx.x & 31;
    const int b = blockIdx.x * 4 + w;
    const int dir = blockIdx.y;

    __shared__ __align__(16) float hb[4][2][32];

    const float* wh = Whh + dir * 96 * 32;
    const float* bh = bhh + dir * 96;

    float whr[32], whz[32], whn[32];
#pragma unroll
    for (int k = 0; k < 32; k += 4) {
        float4 a = *(const float4*)&wh[(lane) * 32 + k];
        whr[k] = a.x; whr[k + 1] = a.y; whr[k + 2] = a.z; whr[k + 3] = a.w;
        float4 c = *(const float4*)&wh[(32 + lane) * 32 + k];
        whz[k] = c.x; whz[k + 1] = c.y; whz[k + 2] = c.z; whz[k + 3] = c.w;
        float4 d = *(const float4*)&wh[(64 + lane) * 32 + k];
        whn[k] = d.x; whn[k + 1] = d.y; whn[k + 2] = d.z; whn[k + 3] = d.w;
    }
    const float br = bh[lane];
    const float bz = bh[32 + lane];
    const float bn = bh[64 + lane];

    const float* xgb = g_xg + (size_t)b * TT * 192 + dir * 96 + lane;
    float* outb = out + (size_t)b * TT * 64 + dir * 32 + lane;
    const int sd = dir ? -1 : 1;
    int te = dir ? (TT - 1) : 0;

    // Prefetch ring, distance 4.
    float pxr[4], pxz[4], pxn[4];
#pragma unroll
    for (int u = 0; u < 4; u++) {
        const float* p = xgb + (size_t)(te + sd * u) * 192;
        pxr[u] = p[0]; pxz[u] = p[32]; pxn[u] = p[64];
    }

    float h = 0.0f;
    hb[w][0][lane] = 0.0f;
    __syncwarp();

    for (int tb = 0; tb < TT; tb += 4) {
#pragma unroll
        for (int u = 0; u < 4; u++) {
            const int t = tb + u;
            const int tp = (t + 4 < TT) ? (te + sd * 4) : te;
            const float* p = xgb + (size_t)tp * 192;
            const float fr = p[0], fz = p[32], fn = p[64];

            float sr0 = pxr[u] + br, sr1 = 0.f;
            float sz0 = pxz[u] + bz, sz1 = 0.f;
            float sn0 = bn, sn1 = 0.f;

            const float4* h4 = (const float4*)hb[w][t & 1];
#pragma unroll
            for (int c = 0; c < 8; c++) {
                float4 v = h4[c];
                sr0 = fmaf(v.x, whr[4 * c + 0], sr0);
                sr0 = fmaf(v.y, whr[4 * c + 1], sr0);
                sr1 = fmaf(v.z, whr[4 * c + 2], sr1);
                sr1 = fmaf(v.w, whr[4 * c + 3], sr1);
                sz0 = fmaf(v.x, whz[4 * c + 0], sz0);
                sz0 = fmaf(v.y, whz[4 * c + 1], sz0);
                sz1 = fmaf(v.z, whz[4 * c + 2], sz1);
                sz1 = fmaf(v.w, whz[4 * c + 3], sz1);
                sn0 = fmaf(v.x, whn[4 * c + 0], sn0);
                sn0 = fmaf(v.y, whn[4 * c + 1], sn0);
                sn1 = fmaf(v.z, whn[4 * c + 2], sn1);
                sn1 = fmaf(v.w, whn[4 * c + 3], sn1);
            }
            const float r = sigf(sr0 + sr1);
            const float z = sigf(sz0 + sz1);
            const float n = tanh_fast(fmaf(r, sn0 + sn1, pxn[u]));
            h = fmaf(z, h - n, n);

            hb[w][(t + 1) & 1][lane] = h;
            outb[(size_t)te * 64] = h;
            pxr[u] = fr; pxz[u] = fz; pxn[u] = fn;
            te += sd;
            __syncwarp();
        }
    }
}

// ---------------------------------------------------------------------------
// Final FC: y = tanh(out @ Wfc.T + bfc). Warp per row, shuffle reduction.
// ---------------------------------------------------------------------------
__global__ __launch_bounds__(256) void fc_kernel(
    const float* __restrict__ Wfc, const float* __restrict__ bfc,
    float* __restrict__ outp)
{
    const float* in = g_buf0;  // layer 2 output
    const int lane = threadIdx.x & 31;
    const int warp = (blockIdx.x * blockDim.x + threadIdx.x) >> 5;
    const int nwarps = (gridDim.x * blockDim.x) >> 5;

    const float w0a = __ldg(&Wfc[2 * lane]),      w0b = __ldg(&Wfc[2 * lane + 1]);
    const float w1a = __ldg(&Wfc[64 + 2 * lane]), w1b = __ldg(&Wfc[64 + 2 * lane + 1]);
    const float b0 = __ldg(&bfc[0]), b1 = __ldg(&bfc[1]);

    const int nrows = BB * TT;
    for (int row = warp; row < nrows; row += nwarps) {
        float2 xv = *(const float2*)&in[(size_t)row * 64 + 2 * lane];
        float y0 = fmaf(xv.y, w0b, xv.x * w0a);
        float y1 = fmaf(xv.y, w1b, xv.x * w1a);
#pragma unroll
        for (int o = 16; o > 0; o >>= 1) {
            y0 += __shfl_xor_sync(0xFFFFFFFFu, y0, o);
            y1 += __shfl_xor_sync(0xFFFFFFFFu, y1, o);
        }
        if (lane == 0) {
            float2 r;
            r.x = tanh_fast(y0 + b0);
            r.y = tanh_fast(y1 + b1);
            *(float2*)&outp[(size_t)row * 2] = r;
        }
    }
}

// ---------------------------------------------------------------------------
extern "C" void kernel_launch(void* const* d_in, const int* in_sizes, int n_in,
                              void* d_out, int out_size)
{
    const float* x    = (const float*)d_in[0];
    const float* Wih0 = (const float*)d_in[1];
    const float* Whh0 = (const float*)d_in[2];
    const float* bih0 = (const float*)d_in[3];
    const float* bhh0 = (const float*)d_in[4];
    const float* Wih  = (const float*)d_in[5];
    const float* Whh  = (const float*)d_in[6];
    const float* bih  = (const float*)d_in[7];
    const float* bhh  = (const float*)d_in[8];
    const float* Wfc  = (const float*)d_in[9];
    const float* bfc  = (const float*)d_in[10];
    float* out = (float*)d_out;

    const int MB = (BB * TT) / 64;  // xgemm grid.x

    // Layer 0 -> buf0
    gru_l0<<<dim3(BB / 4, 2), 128>>>(x, Wih0, Whh0, bih0, bhh0);
    // Layer 1: buf0 -> xg -> buf1
    xgemm<<<dim3(MB, 2), 256>>>(0, Wih, bih);
    gru_rec<<<dim3(BB / 4, 2), 128>>>(1, Whh, bhh);
    // Layer 2: buf1 -> xg -> buf0
    xgemm<<<dim3(MB, 2), 256>>>(1, Wih + 192 * 64, bih + 192);
    gru_rec<<<dim3(BB / 4, 2), 128>>>(0, Whh + 192 * 32, bhh + 192);
    // FC
    fc_kernel<<<2048, 256>>>(Wfc, bfc, out);
}

// round 6
// speedup vs baseline: 1.4255x; 1.2211x over previous
#include <cuda_runtime.h>
#include <cuda_bf16.h>

#define BB 16384
#define TT 64

// Ping-pong layer buffers: [B][T][64] (fwd in [0:32), bwd in [32:64))
__device__ float g_buf0[BB * TT * 64];
__device__ float g_buf1[BB * TT * 64];
// Input-gate pre-activations for the current layer: [B][T][192]
// col g = dir*96 + (gate*32 + j), includes bih.
__device__ float g_xg[(size_t)BB * TT * 192];

__device__ __forceinline__ float sigf(float x) {
    return __fdividef(1.0f, 1.0f + __expf(-x));
}
__device__ __forceinline__ float tanh_fast(float x) {
    float e = __expf(-2.0f * x);
    return __fdividef(1.0f - e, 1.0f + e);
}

// ---------------------------------------------------------------------------
// Layer 0: input K=2. One warp per (batch, dir). Lane j owns hidden unit j,
// computes all 3 gates. Whh rows in registers; x staged in smem once;
// h broadcast via smem double buffer, one __syncwarp per step.
// ---------------------------------------------------------------------------
__global__ __launch_bounds__(128) void gru_l0(
    const float* __restrict__ x,
    const float* __restrict__ Wih0, const float* __restrict__ Whh0,
    const float* __restrict__ bih0, const float* __restrict__ bhh0)
{
    const int w = threadIdx.x >> 5, lane = threadIdx.x & 31;
    const int b = blockIdx.x * 4 + w;
    const int dir = blockIdx.y;

    __shared__ __align__(16) float hb[4][2][32];
    __shared__ __align__(16) float xs[4][128];   // whole input sequence per warp

    const float* wi = Wih0 + dir * 96 * 2;
    const float* wh = Whh0 + dir * 96 * 32;
    const float* bi = bih0 + dir * 96;
    const float* bh = bhh0 + dir * 96;

    {
        float4 v = *(const float4*)(x + (size_t)b * 128 + lane * 4);
        *(float4*)&xs[w][lane * 4] = v;
    }

    const float wx0 = wi[(lane) * 2 + 0],      wx1 = wi[(lane) * 2 + 1];
    const float wz0 = wi[(32 + lane) * 2 + 0], wz1 = wi[(32 + lane) * 2 + 1];
    const float wn0 = wi[(64 + lane) * 2 + 0], wn1 = wi[(64 + lane) * 2 + 1];

    float whr[32], whz[32], whn[32];
#pragma unroll
    for (int k = 0; k < 32; k += 4) {
        float4 a = *(const float4*)&wh[(lane) * 32 + k];
        whr[k] = a.x; whr[k + 1] = a.y; whr[k + 2] = a.z; whr[k + 3] = a.w;
        float4 c = *(const float4*)&wh[(32 + lane) * 32 + k];
        whz[k] = c.x; whz[k + 1] = c.y; whz[k + 2] = c.z; whz[k + 3] = c.w;
        float4 d = *(const float4*)&wh[(64 + lane) * 32 + k];
        whn[k] = d.x; whn[k + 1] = d.y; whn[k + 2] = d.z; whn[k + 3] = d.w;
    }
    const float br  = bi[lane] + bh[lane];
    const float bz  = bi[32 + lane] + bh[32 + lane];
    const float bxn = bi[64 + lane];
    const float bhn = bh[64 + lane];

    float h = 0.0f;
    hb[w][0][lane] = 0.0f;
    __syncwarp();

    float* outp = g_buf0 + (size_t)b * TT * 64 + dir * 32 + lane;

    for (int t = 0; t < TT; t++) {
        const int te = dir ? (TT - 1 - t) : t;
        const float x0 = xs[w][te * 2 + 0];
        const float x1 = xs[w][te * 2 + 1];

        float sr0 = fmaf(x1, wx1, fmaf(x0, wx0, br)),  sr1 = 0.f;
        float sz0 = fmaf(x1, wz1, fmaf(x0, wz0, bz)),  sz1 = 0.f;
        float sn0 = bhn, sn1 = 0.f;

        const float4* h4 = (const float4*)hb[w][t & 1];
#pragma unroll
        for (int c = 0; c < 8; c++) {
            float4 v = h4[c];
            sr0 = fmaf(v.x, whr[4 * c + 0], sr0);
            sr0 = fmaf(v.y, whr[4 * c + 1], sr0);
            sr1 = fmaf(v.z, whr[4 * c + 2], sr1);
            sr1 = fmaf(v.w, whr[4 * c + 3], sr1);
            sz0 = fmaf(v.x, whz[4 * c + 0], sz0);
            sz0 = fmaf(v.y, whz[4 * c + 1], sz0);
            sz1 = fmaf(v.z, whz[4 * c + 2], sz1);
            sz1 = fmaf(v.w, whz[4 * c + 3], sz1);
            sn0 = fmaf(v.x, whn[4 * c + 0], sn0);
            sn0 = fmaf(v.y, whn[4 * c + 1], sn0);
            sn1 = fmaf(v.z, whn[4 * c + 2], sn1);
            sn1 = fmaf(v.w, whn[4 * c + 3], sn1);
        }
        const float r = sigf(sr0 + sr1);
        const float z = sigf(sz0 + sz1);
        const float n = tanh_fast(fmaf(r, sn0 + sn1, fmaf(x1, wn1, fmaf(x0, wn0, bxn))));
        h = fmaf(z, h - n, n);

        hb[w][(t + 1) & 1][lane] = h;
        outp[(size_t)te * 64] = h;
        __syncwarp();
    }
}

// ---------------------------------------------------------------------------
// Tensor-core input GEMM for layers 1/2 (bf16 3-pass Markidis split):
//   xg[m][g] = sum_k in[m][k] * W[g][k] + bih[g],  m < B*T, g < 192, K = 64.
// A = A_hi + A_lo (bf16), W = W_hi + W_lo (bf16);
//   acc += A_hi*W_hi + A_hi*W_lo + A_lo*W_hi   (fp32 acc; error ~2^-16)
// Block 256 thr (8 warps), tile M=64 x N=96 (grid.y = dir). Warp tile 16x48.
// Smem rows padded to 72 bf16 (36 words) -> fragment LDS.32 conflict-free.
// ---------------------------------------------------------------------------
__device__ __forceinline__ void mma16816(float* c, const unsigned* a,
                                         unsigned b0, unsigned b1) {
    asm volatile(
        "mma.sync.aligned.m16n8k16.row.col.f32.bf16.bf16.f32 "
        "{%0,%1,%2,%3}, {%4,%5,%6,%7}, {%8,%9}, {%0,%1,%2,%3};"
        : "+f"(c[0]), "+f"(c[1]), "+f"(c[2]), "+f"(c[3])
        : "r"(a[0]), "r"(a[1]), "r"(a[2]), "r"(a[3]), "r"(b0), "r"(b1));
}

#define APAD 72  // bf16 elems per smem row (64 + 8 pad) = 36 words

__global__ __launch_bounds__(256) void xgemm_mma(
    int srcbuf,
    const float* __restrict__ W,     // [192][64] for this layer
    const float* __restrict__ bias)  // [192]
{
    const float* in = srcbuf ? g_buf1 : g_buf0;

    __shared__ __align__(16) __nv_bfloat16 As_hi[64][APAD];
    __shared__ __align__(16) __nv_bfloat16 As_lo[64][APAD];
    __shared__ __align__(16) __nv_bfloat16 Ws_hi[96][APAD];
    __shared__ __align__(16) __nv_bfloat16 Ws_lo[96][APAD];
    __shared__ float Bs[96];

    const int tid = threadIdx.x;
    const size_t m0 = (size_t)blockIdx.x * 64;
    const int c0g = blockIdx.y * 96;

    // Stage A tile split hi/lo: in[m0+r][k4..k4+3]
    for (int q = tid; q < 64 * 16; q += 256) {
        const int r = q >> 4, k4 = (q & 15) << 2;
        float4 v = *(const float4*)&in[(m0 + r) * 64 + k4];
        __nv_bfloat16 hx = __float2bfloat16(v.x), hy = __float2bfloat16(v.y);
        __nv_bfloat16 hz = __float2bfloat16(v.z), hw = __float2bfloat16(v.w);
        *(__nv_bfloat162*)&As_hi[r][k4]     = __nv_bfloat162(hx, hy);
        *(__nv_bfloat162*)&As_hi[r][k4 + 2] = __nv_bfloat162(hz, hw);
        *(__nv_bfloat162*)&As_lo[r][k4] = __nv_bfloat162(
            __float2bfloat16(v.x - __bfloat162float(hx)),
            __float2bfloat16(v.y - __bfloat162float(hy)));
        *(__nv_bfloat162*)&As_lo[r][k4 + 2] = __nv_bfloat162(
            __float2bfloat16(v.z - __bfloat162float(hz)),
            __float2bfloat16(v.w - __bfloat162float(hw)));
    }
    // Stage W half split hi/lo: W[c0g+g][k4..]
    for (int q = tid; q < 96 * 16; q += 256) {
        const int g = q >> 4, k4 = (q & 15) << 2;
        float4 v = *(const float4*)&W[(size_t)(c0g + g) * 64 + k4];
        __nv_bfloat16 hx = __float2bfloat16(v.x), hy = __float2bfloat16(v.y);
        __nv_bfloat16 hz = __float2bfloat16(v.z), hw = __float2bfloat16(v.w);
        *(__nv_bfloat162*)&Ws_hi[g][k4]     = __nv_bfloat162(hx, hy);
        *(__nv_bfloat162*)&Ws_hi[g][k4 + 2] = __nv_bfloat162(hz, hw);
        *(__nv_bfloat162*)&Ws_lo[g][k4] = __nv_bfloat162(
            __float2bfloat16(v.x - __bfloat162float(hx)),
            __float2bfloat16(v.y - __bfloat162float(hy)));
        *(__nv_bfloat162*)&Ws_lo[g][k4 + 2] = __nv_bfloat162(
            __float2bfloat16(v.z - __bfloat162float(hz)),
            __float2bfloat16(v.w - __bfloat162float(hw)));
    }
    if (tid < 96) Bs[tid] = bias[c0g + tid];
    __syncthreads();

    const int wid = tid >> 5, lane = tid & 31;
    const int mrow0 = (wid >> 1) * 16;          // 0,16,32,48
    const int ncol0 = (wid & 1) * 48;           // 0,48
    const int g = lane >> 2;                    // 0..7
    const int t2 = (lane & 3) * 2;              // 0,2,4,6

    float acc[6][4];
#pragma unroll
    for (int j = 0; j < 6; j++)
#pragma unroll
        for (int i = 0; i < 4; i++) acc[j][i] = 0.0f;

#pragma unroll
    for (int ks = 0; ks < 4; ks++) {
        const int k0 = ks * 16;
        unsigned a_hi[4], a_lo[4];
        a_hi[0] = *(const unsigned*)&As_hi[mrow0 + g][k0 + t2];
        a_hi[1] = *(const unsigned*)&As_hi[mrow0 + g + 8][k0 + t2];
        a_hi[2] = *(const unsigned*)&As_hi[mrow0 + g][k0 + t2 + 8];
        a_hi[3] = *(const unsigned*)&As_hi[mrow0 + g + 8][k0 + t2 + 8];
        a_lo[0] = *(const unsigned*)&As_lo[mrow0 + g][k0 + t2];
        a_lo[1] = *(const unsigned*)&As_lo[mrow0 + g + 8][k0 + t2];
        a_lo[2] = *(const unsigned*)&As_lo[mrow0 + g][k0 + t2 + 8];
        a_lo[3] = *(const unsigned*)&As_lo[mrow0 + g + 8][k0 + t2 + 8];
#pragma unroll
        for (int j = 0; j < 6; j++) {
            const int n = ncol0 + j * 8 + g;
            unsigned bh0 = *(const unsigned*)&Ws_hi[n][k0 + t2];
            unsigned bh1 = *(const unsigned*)&Ws_hi[n][k0 + t2 + 8];
            unsigned bl0 = *(const unsigned*)&Ws_lo[n][k0 + t2];
            unsigned bl1 = *(const unsigned*)&Ws_lo[n][k0 + t2 + 8];
            mma16816(acc[j], a_hi, bh0, bh1);
            mma16816(acc[j], a_hi, bl0, bl1);
            mma16816(acc[j], a_lo, bh0, bh1);
        }
    }

    // Epilogue: add bias, store fp32 to g_xg.
#pragma unroll
    for (int j = 0; j < 6; j++) {
        const int cb = ncol0 + j * 8 + t2;      // local col of acc[j][0]
        const float b0 = Bs[cb], b1 = Bs[cb + 1];
        float* o0 = g_xg + (m0 + mrow0 + g) * 192 + c0g + cb;
        float* o1 = g_xg + (m0 + mrow0 + g + 8) * 192 + c0g + cb;
        float2 v0; v0.x = acc[j][0] + b0; v0.y = acc[j][1] + b1;
        float2 v1; v1.x = acc[j][2] + b0; v1.y = acc[j][3] + b1;
        *(float2*)o0 = v0;
        *(float2*)o1 = v1;
    }
}

// ---------------------------------------------------------------------------
// Recurrence for layers 1/2. One warp per (batch, dir); lane j owns unit j,
// all 3 gates (96 weight regs, 96 FFMA/step). xg read with distance-4
// register-ring prefetch. No block barriers.
// ---------------------------------------------------------------------------
__global__ __launch_bounds__(128) void gru_rec(
    int dstbuf,
    const float* __restrict__ Whh,   // [2][96][32] for this layer
    const float* __restrict__ bhh)   // [192]
{
    float* out = dstbuf ? g_buf1 : g_buf0;

    const int w = threadIdx.x >> 5, lane = threadIdx.x & 31;
    const int b = blockIdx.x * 4 + w;
    const int dir = blockIdx.y;

    __shared__ __align__(16) float hb[4][2][32];

    const float* wh = Whh + dir * 96 * 32;
    const float* bh = bhh + dir * 96;

    float whr[32], whz[32], whn[32];
#pragma unroll
    for (int k = 0; k < 32; k += 4) {
        float4 a = *(const float4*)&wh[(lane) * 32 + k];
        whr[k] = a.x; whr[k + 1] = a.y; whr[k + 2] = a.z; whr[k + 3] = a.w;
        float4 c = *(const float4*)&wh[(32 + lane) * 32 + k];
        whz[k] = c.x; whz[k + 1] = c.y; whz[k + 2] = c.z; whz[k + 3] = c.w;
        float4 d = *(const float4*)&wh[(64 + lane) * 32 + k];
        whn[k] = d.x; whn[k + 1] = d.y; whn[k + 2] = d.z; whn[k + 3] = d.w;
    }
    const float br = bh[lane];
    const float bz = bh[32 + lane];
    const float bn = bh[64 + lane];

    const float* xgb = g_xg + (size_t)b * TT * 192 + dir * 96 + lane;
    float* outb = out + (size_t)b * TT * 64 + dir * 32 + lane;
    const int sd = dir ? -1 : 1;
    int te = dir ? (TT - 1) : 0;

    // Prefetch ring, distance 4.
    float pxr[4], pxz[4], pxn[4];
#pragma unroll
    for (int u = 0; u < 4; u++) {
        const float* p = xgb + (size_t)(te + sd * u) * 192;
        pxr[u] = p[0]; pxz[u] = p[32]; pxn[u] = p[64];
    }

    float h = 0.0f;
    hb[w][0][lane] = 0.0f;
    __syncwarp();

    for (int tb = 0; tb < TT; tb += 4) {
#pragma unroll
        for (int u = 0; u < 4; u++) {
            const int t = tb + u;
            const int tp = (t + 4 < TT) ? (te + sd * 4) : te;
            const float* p = xgb + (size_t)tp * 192;
            const float fr = p[0], fz = p[32], fn = p[64];

            float sr0 = pxr[u] + br, sr1 = 0.f;
            float sz0 = pxz[u] + bz, sz1 = 0.f;
            float sn0 = bn, sn1 = 0.f;

            const float4* h4 = (const float4*)hb[w][t & 1];
#pragma unroll
            for (int c = 0; c < 8; c++) {
                float4 v = h4[c];
                sr0 = fmaf(v.x, whr[4 * c + 0], sr0);
                sr0 = fmaf(v.y, whr[4 * c + 1], sr0);
                sr1 = fmaf(v.z, whr[4 * c + 2], sr1);
                sr1 = fmaf(v.w, whr[4 * c + 3], sr1);
                sz0 = fmaf(v.x, whz[4 * c + 0], sz0);
                sz0 = fmaf(v.y, whz[4 * c + 1], sz0);
                sz1 = fmaf(v.z, whz[4 * c + 2], sz1);
                sz1 = fmaf(v.w, whz[4 * c + 3], sz1);
                sn0 = fmaf(v.x, whn[4 * c + 0], sn0);
                sn0 = fmaf(v.y, whn[4 * c + 1], sn0);
                sn1 = fmaf(v.z, whn[4 * c + 2], sn1);
                sn1 = fmaf(v.w, whn[4 * c + 3], sn1);
            }
            const float r = sigf(sr0 + sr1);
            const float z = sigf(sz0 + sz1);
            const float n = tanh_fast(fmaf(r, sn0 + sn1, pxn[u]));
            h = fmaf(z, h - n, n);

            hb[w][(t + 1) & 1][lane] = h;
            outb[(size_t)te * 64] = h;
            pxr[u] = fr; pxz[u] = fz; pxn[u] = fn;
            te += sd;
            __syncwarp();
        }
    }
}

// ---------------------------------------------------------------------------
// Final FC: y = tanh(out @ Wfc.T + bfc). Warp per row, shuffle reduction.
// ---------------------------------------------------------------------------
__global__ __launch_bounds__(256) void fc_kernel(
    const float* __restrict__ Wfc, const float* __restrict__ bfc,
    float* __restrict__ outp)
{
    const float* in = g_buf0;  // layer 2 output
    const int lane = threadIdx.x & 31;
    const int warp = (blockIdx.x * blockDim.x + threadIdx.x) >> 5;
    const int nwarps = (gridDim.x * blockDim.x) >> 5;

    const float w0a = __ldg(&Wfc[2 * lane]),      w0b = __ldg(&Wfc[2 * lane + 1]);
    const float w1a = __ldg(&Wfc[64 + 2 * lane]), w1b = __ldg(&Wfc[64 + 2 * lane + 1]);
    const float b0 = __ldg(&bfc[0]), b1 = __ldg(&bfc[1]);

    const int nrows = BB * TT;
    for (int row = warp; row < nrows; row += nwarps) {
        float2 xv = *(const float2*)&in[(size_t)row * 64 + 2 * lane];
        float y0 = fmaf(xv.y, w0b, xv.x * w0a);
        float y1 = fmaf(xv.y, w1b, xv.x * w1a);
#pragma unroll
        for (int o = 16; o > 0; o >>= 1) {
            y0 += __shfl_xor_sync(0xFFFFFFFFu, y0, o);
            y1 += __shfl_xor_sync(0xFFFFFFFFu, y1, o);
        }
        if (lane == 0) {
            float2 r;
            r.x = tanh_fast(y0 + b0);
            r.y = tanh_fast(y1 + b1);
            *(float2*)&outp[(size_t)row * 2] = r;
        }
    }
}

// ---------------------------------------------------------------------------
extern "C" void kernel_launch(void* const* d_in, const int* in_sizes, int n_in,
                              void* d_out, int out_size)
{
    const float* x    = (const float*)d_in[0];
    const float* Wih0 = (const float*)d_in[1];
    const float* Whh0 = (const float*)d_in[2];
    const float* bih0 = (const float*)d_in[3];
    const float* bhh0 = (const float*)d_in[4];
    const float* Wih  = (const float*)d_in[5];
    const float* Whh  = (const float*)d_in[6];
    const float* bih  = (const float*)d_in[7];
    const float* bhh  = (const float*)d_in[8];
    const float* Wfc  = (const float*)d_in[9];
    const float* bfc  = (const float*)d_in[10];
    float* out = (float*)d_out;

    const int MB = (BB * TT) / 64;  // GEMM grid.x

    // Layer 0 -> buf0
    gru_l0<<<dim3(BB / 4, 2), 128>>>(x, Wih0, Whh0, bih0, bhh0);
    // Layer 1: buf0 -> xg -> buf1
    xgemm_mma<<<dim3(MB, 2), 256>>>(0, Wih, bih);
    gru_rec<<<dim3(BB / 4, 2), 128>>>(1, Whh, bhh);
    // Layer 2: buf1 -> xg -> buf0
    xgemm_mma<<<dim3(MB, 2), 256>>>(1, Wih + 192 * 64, bih + 192);
    gru_rec<<<dim3(BB / 4, 2), 128>>>(0, Whh + 192 * 32, bhh + 192);
    // FC
    fc_kernel<<<2048, 256>>>(Wfc, bfc, out);
}

// round 7
// speedup vs baseline: 1.5081x; 1.0579x over previous
#include <cuda_runtime.h>
#include <cuda_bf16.h>

#define BB 16384
#define TT 64

// Ping-pong layer buffers: [B][T][64] (fwd in [0:32), bwd in [32:64))
__device__ float g_buf0[BB * TT * 64];
__device__ float g_buf1[BB * TT * 64];
// Input-gate pre-activations for the current layer: [B][T][192]
// col g = dir*96 + (gate*32 + j), includes bih.
__device__ float g_xg[(size_t)BB * TT * 192];

__device__ __forceinline__ float sigf(float x) {
    return __fdividef(1.0f, 1.0f + __expf(-x));
}
__device__ __forceinline__ float tanh_fast(float x) {
    float e = __expf(-2.0f * x);
    return __fdividef(1.0f - e, 1.0f + e);
}

// ---------------------------------------------------------------------------
// Layer 0: input K=2. One warp per (batch, dir). Lane j owns hidden unit j,
// computes all 3 gates. Whh rows in registers; x staged in smem once;
// h broadcast via smem double buffer, one __syncwarp per step.
// ---------------------------------------------------------------------------
__global__ __launch_bounds__(128) void gru_l0(
    const float* __restrict__ x,
    const float* __restrict__ Wih0, const float* __restrict__ Whh0,
    const float* __restrict__ bih0, const float* __restrict__ bhh0)
{
    const int w = threadIdx.x >> 5, lane = threadIdx.x & 31;
    const int b = blockIdx.x * 4 + w;
    const int dir = blockIdx.y;

    __shared__ __align__(16) float hb[4][2][32];
    __shared__ __align__(16) float xs[4][128];   // whole input sequence per warp

    const float* wi = Wih0 + dir * 96 * 2;
    const float* wh = Whh0 + dir * 96 * 32;
    const float* bi = bih0 + dir * 96;
    const float* bh = bhh0 + dir * 96;

    {
        float4 v = *(const float4*)(x + (size_t)b * 128 + lane * 4);
        *(float4*)&xs[w][lane * 4] = v;
    }

    const float wx0 = wi[(lane) * 2 + 0],      wx1 = wi[(lane) * 2 + 1];
    const float wz0 = wi[(32 + lane) * 2 + 0], wz1 = wi[(32 + lane) * 2 + 1];
    const float wn0 = wi[(64 + lane) * 2 + 0], wn1 = wi[(64 + lane) * 2 + 1];

    float whr[32], whz[32], whn[32];
#pragma unroll
    for (int k = 0; k < 32; k += 4) {
        float4 a = *(const float4*)&wh[(lane) * 32 + k];
        whr[k] = a.x; whr[k + 1] = a.y; whr[k + 2] = a.z; whr[k + 3] = a.w;
        float4 c = *(const float4*)&wh[(32 + lane) * 32 + k];
        whz[k] = c.x; whz[k + 1] = c.y; whz[k + 2] = c.z; whz[k + 3] = c.w;
        float4 d = *(const float4*)&wh[(64 + lane) * 32 + k];
        whn[k] = d.x; whn[k + 1] = d.y; whn[k + 2] = d.z; whn[k + 3] = d.w;
    }
    const float br  = bi[lane] + bh[lane];
    const float bz  = bi[32 + lane] + bh[32 + lane];
    const float bxn = bi[64 + lane];
    const float bhn = bh[64 + lane];

    float h = 0.0f;
    hb[w][0][lane] = 0.0f;
    __syncwarp();

    float* outp = g_buf0 + (size_t)b * TT * 64 + dir * 32 + lane;

    for (int t = 0; t < TT; t++) {
        const int te = dir ? (TT - 1 - t) : t;
        const float x0 = xs[w][te * 2 + 0];
        const float x1 = xs[w][te * 2 + 1];

        float sr0 = fmaf(x1, wx1, fmaf(x0, wx0, br)),  sr1 = 0.f;
        float sz0 = fmaf(x1, wz1, fmaf(x0, wz0, bz)),  sz1 = 0.f;
        float sn0 = bhn, sn1 = 0.f;

        const float4* h4 = (const float4*)hb[w][t & 1];
#pragma unroll
        for (int c = 0; c < 8; c++) {
            float4 v = h4[c];
            sr0 = fmaf(v.x, whr[4 * c + 0], sr0);
            sr0 = fmaf(v.y, whr[4 * c + 1], sr0);
            sr1 = fmaf(v.z, whr[4 * c + 2], sr1);
            sr1 = fmaf(v.w, whr[4 * c + 3], sr1);
            sz0 = fmaf(v.x, whz[4 * c + 0], sz0);
            sz0 = fmaf(v.y, whz[4 * c + 1], sz0);
            sz1 = fmaf(v.z, whz[4 * c + 2], sz1);
            sz1 = fmaf(v.w, whz[4 * c + 3], sz1);
            sn0 = fmaf(v.x, whn[4 * c + 0], sn0);
            sn0 = fmaf(v.y, whn[4 * c + 1], sn0);
            sn1 = fmaf(v.z, whn[4 * c + 2], sn1);
            sn1 = fmaf(v.w, whn[4 * c + 3], sn1);
        }
        const float r = sigf(sr0 + sr1);
        const float z = sigf(sz0 + sz1);
        const float n = tanh_fast(fmaf(r, sn0 + sn1, fmaf(x1, wn1, fmaf(x0, wn0, bxn))));
        h = fmaf(z, h - n, n);

        hb[w][(t + 1) & 1][lane] = h;
        outp[(size_t)te * 64] = h;
        __syncwarp();
    }
}

// ---------------------------------------------------------------------------
// Tensor-core input GEMM for layers 1/2 (bf16 3-pass Markidis split):
//   xg[m][g] = sum_k in[m][k] * W[g][k] + bih[g],  m < B*T, g < 192, K = 64.
// acc += A_hi*W_hi + A_hi*W_lo + A_lo*W_hi  (fp32 acc; error ~2^-16).
// Block 256 thr (8 warps), tile M=64 x N=96 (grid.y = dir). Warp tile 16x48.
// ldmatrix.x4 fragment loads (8 LDSM vs 32 LDS.32 per k16-step);
// launch_bounds(256,4) forces <=64 regs -> 4 blocks/SM (50% occ).
// ---------------------------------------------------------------------------
__device__ __forceinline__ void mma16816(float* c, const unsigned* a,
                                         unsigned b0, unsigned b1) {
    asm volatile(
        "mma.sync.aligned.m16n8k16.row.col.f32.bf16.bf16.f32 "
        "{%0,%1,%2,%3}, {%4,%5,%6,%7}, {%8,%9}, {%0,%1,%2,%3};"
        : "+f"(c[0]), "+f"(c[1]), "+f"(c[2]), "+f"(c[3])
        : "r"(a[0]), "r"(a[1]), "r"(a[2]), "r"(a[3]), "r"(b0), "r"(b1));
}
__device__ __forceinline__ void ldsm4(unsigned* r, unsigned addr) {
    asm volatile(
        "ldmatrix.sync.aligned.m8n8.x4.shared.b16 {%0,%1,%2,%3}, [%4];"
        : "=r"(r[0]), "=r"(r[1]), "=r"(r[2]), "=r"(r[3]) : "r"(addr));
}

#define APAD 72  // bf16 elems per smem row (64 + 8 pad) = 144 B (16B-aligned)

__global__ __launch_bounds__(256, 4) void xgemm_mma(
    int srcbuf,
    const float* __restrict__ W,     // [192][64] for this layer
    const float* __restrict__ bias)  // [192]
{
    const float* in = srcbuf ? g_buf1 : g_buf0;

    __shared__ __align__(16) __nv_bfloat16 As_hi[64][APAD];
    __shared__ __align__(16) __nv_bfloat16 As_lo[64][APAD];
    __shared__ __align__(16) __nv_bfloat16 Ws_hi[96][APAD];
    __shared__ __align__(16) __nv_bfloat16 Ws_lo[96][APAD];
    __shared__ float Bs[96];

    const int tid = threadIdx.x;
    const size_t m0 = (size_t)blockIdx.x * 64;
    const int c0g = blockIdx.y * 96;

    // Stage A tile split hi/lo: in[m0+r][k4..k4+3]
    for (int q = tid; q < 64 * 16; q += 256) {
        const int r = q >> 4, k4 = (q & 15) << 2;
        float4 v = *(const float4*)&in[(m0 + r) * 64 + k4];
        __nv_bfloat16 hx = __float2bfloat16(v.x), hy = __float2bfloat16(v.y);
        __nv_bfloat16 hz = __float2bfloat16(v.z), hw = __float2bfloat16(v.w);
        *(__nv_bfloat162*)&As_hi[r][k4]     = __nv_bfloat162(hx, hy);
        *(__nv_bfloat162*)&As_hi[r][k4 + 2] = __nv_bfloat162(hz, hw);
        *(__nv_bfloat162*)&As_lo[r][k4] = __nv_bfloat162(
            __float2bfloat16(v.x - __bfloat162float(hx)),
            __float2bfloat16(v.y - __bfloat162float(hy)));
        *(__nv_bfloat162*)&As_lo[r][k4 + 2] = __nv_bfloat162(
            __float2bfloat16(v.z - __bfloat162float(hz)),
            __float2bfloat16(v.w - __bfloat162float(hw)));
    }
    // Stage W half split hi/lo: W[c0g+g][k4..]
    for (int q = tid; q < 96 * 16; q += 256) {
        const int g = q >> 4, k4 = (q & 15) << 2;
        float4 v = *(const float4*)&W[(size_t)(c0g + g) * 64 + k4];
        __nv_bfloat16 hx = __float2bfloat16(v.x), hy = __float2bfloat16(v.y);
        __nv_bfloat16 hz = __float2bfloat16(v.z), hw = __float2bfloat16(v.w);
        *(__nv_bfloat162*)&Ws_hi[g][k4]     = __nv_bfloat162(hx, hy);
        *(__nv_bfloat162*)&Ws_hi[g][k4 + 2] = __nv_bfloat162(hz, hw);
        *(__nv_bfloat162*)&Ws_lo[g][k4] = __nv_bfloat162(
            __float2bfloat16(v.x - __bfloat162float(hx)),
            __float2bfloat16(v.y - __bfloat162float(hy)));
        *(__nv_bfloat162*)&Ws_lo[g][k4 + 2] = __nv_bfloat162(
            __float2bfloat16(v.z - __bfloat162float(hz)),
            __float2bfloat16(v.w - __bfloat162float(hw)));
    }
    if (tid < 96) Bs[tid] = bias[c0g + tid];
    __syncthreads();

    const int wid = tid >> 5, lane = tid & 31;
    const int mrow0 = (wid >> 1) * 16;          // 0,16,32,48
    const int ncol0 = (wid & 1) * 48;           // 0,48
    const int g = lane >> 2;                    // 0..7
    const int t2 = (lane & 3) * 2;              // 0,2,4,6

    // ldmatrix lane addresses (hoisted; advance by 32 B per k16-step).
    // A x4: matrices (rows 0-7,k0),(rows 8-15,k0),(rows 0-7,k0+8),(rows 8-15,k0+8)
    const int a_r  = mrow0 + (lane & 15);
    const int a_kh = (lane >> 4) * 8;
    const unsigned aHi = (unsigned)__cvta_generic_to_shared(&As_hi[a_r][a_kh]);
    const unsigned aLo = (unsigned)__cvta_generic_to_shared(&As_lo[a_r][a_kh]);
    // W x4 for j-pair (j0,j0+1): matrices (j0,k0),(j0,k0+8),(j0+1,k0),(j0+1,k0+8)
    const int w_jj = (lane >> 4) & 1;
    const int w_kh = ((lane >> 3) & 1) * 8;
    unsigned wHi[3], wLo[3];
#pragma unroll
    for (int p = 0; p < 3; p++) {
        const int row = ncol0 + (2 * p + w_jj) * 8 + (lane & 7);
        wHi[p] = (unsigned)__cvta_generic_to_shared(&Ws_hi[row][w_kh]);
        wLo[p] = (unsigned)__cvta_generic_to_shared(&Ws_lo[row][w_kh]);
    }

    float acc[6][4];
#pragma unroll
    for (int j = 0; j < 6; j++)
#pragma unroll
        for (int i = 0; i < 4; i++) acc[j][i] = 0.0f;

#pragma unroll
    for (int ks = 0; ks < 4; ks++) {
        const unsigned koff = ks * 32;  // 16 bf16 = 32 bytes
        unsigned ah[4], al[4];
        ldsm4(ah, aHi + koff);
        ldsm4(al, aLo + koff);
#pragma unroll
        for (int p = 0; p < 3; p++) {
            unsigned bh[4], bl[4];
            ldsm4(bh, wHi[p] + koff);
            ldsm4(bl, wLo[p] + koff);
            mma16816(acc[2 * p],     ah, bh[0], bh[1]);
            mma16816(acc[2 * p],     ah, bl[0], bl[1]);
            mma16816(acc[2 * p],     al, bh[0], bh[1]);
            mma16816(acc[2 * p + 1], ah, bh[2], bh[3]);
            mma16816(acc[2 * p + 1], ah, bl[2], bl[3]);
            mma16816(acc[2 * p + 1], al, bh[2], bh[3]);
        }
    }

    // Epilogue: add bias, store fp32 to g_xg.
#pragma unroll
    for (int j = 0; j < 6; j++) {
        const int cb = ncol0 + j * 8 + t2;      // local col of acc[j][0]
        const float b0 = Bs[cb], b1 = Bs[cb + 1];
        float* o0 = g_xg + (m0 + mrow0 + g) * 192 + c0g + cb;
        float* o1 = g_xg + (m0 + mrow0 + g + 8) * 192 + c0g + cb;
        float2 v0; v0.x = acc[j][0] + b0; v0.y = acc[j][1] + b1;
        float2 v1; v1.x = acc[j][2] + b0; v1.y = acc[j][3] + b1;
        *(float2*)o0 = v0;
        *(float2*)o1 = v1;
    }
}

// ---------------------------------------------------------------------------
// Recurrence for layers 1/2. One warp per (batch, dir); lane j owns unit j,
// all 3 gates (96 weight regs, 96 FFMA/step). xg read with distance-4
// register-ring prefetch. No block barriers.
// ---------------------------------------------------------------------------
__global__ __launch_bounds__(128) void gru_rec(
    int dstbuf,
    const float* __restrict__ Whh,   // [2][96][32] for this layer
    const float* __restrict__ bhh)   // [192]
{
    float* out = dstbuf ? g_buf1 : g_buf0;

    const int w = threadIdx.x >> 5, lane = threadIdx.x & 31;
    const int b = blockIdx.x * 4 + w;
    const int dir = blockIdx.y;

    __shared__ __align__(16) float hb[4][2][32];

    const float* wh = Whh + dir * 96 * 32;
    const float* bh = bhh + dir * 96;

    float whr[32], whz[32], whn[32];
#pragma unroll
    for (int k = 0; k < 32; k += 4) {
        float4 a = *(const float4*)&wh[(lane) * 32 + k];
        whr[k] = a.x; whr[k + 1] = a.y; whr[k + 2] = a.z; whr[k + 3] = a.w;
        float4 c = *(const float4*)&wh[(32 + lane) * 32 + k];
        whz[k] = c.x; whz[k + 1] = c.y; whz[k + 2] = c.z; whz[k + 3] = c.w;
        float4 d = *(const float4*)&wh[(64 + lane) * 32 + k];
        whn[k] = d.x; whn[k + 1] = d.y; whn[k + 2] = d.z; whn[k + 3] = d.w;
    }
    const float br = bh[lane];
    const float bz = bh[32 + lane];
    const float bn = bh[64 + lane];

    const float* xgb = g_xg + (size_t)b * TT * 192 + dir * 96 + lane;
    float* outb = out + (size_t)b * TT * 64 + dir * 32 + lane;
    const int sd = dir ? -1 : 1;
    int te = dir ? (TT - 1) : 0;

    // Prefetch ring, distance 4.
    float pxr[4], pxz[4], pxn[4];
#pragma unroll
    for (int u = 0; u < 4; u++) {
        const float* p = xgb + (size_t)(te + sd * u) * 192;
        pxr[u] = p[0]; pxz[u] = p[32]; pxn[u] = p[64];
    }

    float h = 0.0f;
    hb[w][0][lane] = 0.0f;
    __syncwarp();

    for (int tb = 0; tb < TT; tb += 4) {
#pragma unroll
        for (int u = 0; u < 4; u++) {
            const int t = tb + u;
            const int tp = (t + 4 < TT) ? (te + sd * 4) : te;
            const float* p = xgb + (size_t)tp * 192;
            const float fr = p[0], fz = p[32], fn = p[64];

            float sr0 = pxr[u] + br, sr1 = 0.f;
            float sz0 = pxz[u] + bz, sz1 = 0.f;
            float sn0 = bn, sn1 = 0.f;

            const float4* h4 = (const float4*)hb[w][t & 1];
#pragma unroll
            for (int c = 0; c < 8; c++) {
                float4 v = h4[c];
                sr0 = fmaf(v.x, whr[4 * c + 0], sr0);
                sr0 = fmaf(v.y, whr[4 * c + 1], sr0);
                sr1 = fmaf(v.z, whr[4 * c + 2], sr1);
                sr1 = fmaf(v.w, whr[4 * c + 3], sr1);
                sz0 = fmaf(v.x, whz[4 * c + 0], sz0);
                sz0 = fmaf(v.y, whz[4 * c + 1], sz0);
                sz1 = fmaf(v.z, whz[4 * c + 2], sz1);
                sz1 = fmaf(v.w, whz[4 * c + 3], sz1);
                sn0 = fmaf(v.x, whn[4 * c + 0], sn0);
                sn0 = fmaf(v.y, whn[4 * c + 1], sn0);
                sn1 = fmaf(v.z, whn[4 * c + 2], sn1);
                sn1 = fmaf(v.w, whn[4 * c + 3], sn1);
            }
            const float r = sigf(sr0 + sr1);
            const float z = sigf(sz0 + sz1);
            const float n = tanh_fast(fmaf(r, sn0 + sn1, pxn[u]));
            h = fmaf(z, h - n, n);

            hb[w][(t + 1) & 1][lane] = h;
            outb[(size_t)te * 64] = h;
            pxr[u] = fr; pxz[u] = fz; pxn[u] = fn;
            te += sd;
            __syncwarp();
        }
    }
}

// ---------------------------------------------------------------------------
// Final FC: y = tanh(out @ Wfc.T + bfc). Warp per row, shuffle reduction.
// ---------------------------------------------------------------------------
__global__ __launch_bounds__(256) void fc_kernel(
    const float* __restrict__ Wfc, const float* __restrict__ bfc,
    float* __restrict__ outp)
{
    const float* in = g_buf0;  // layer 2 output
    const int lane = threadIdx.x & 31;
    const int warp = (blockIdx.x * blockDim.x + threadIdx.x) >> 5;
    const int nwarps = (gridDim.x * blockDim.x) >> 5;

    const float w0a = __ldg(&Wfc[2 * lane]),      w0b = __ldg(&Wfc[2 * lane + 1]);
    const float w1a = __ldg(&Wfc[64 + 2 * lane]), w1b = __ldg(&Wfc[64 + 2 * lane + 1]);
    const float b0 = __ldg(&bfc[0]), b1 = __ldg(&bfc[1]);

    const int nrows = BB * TT;
    for (int row = warp; row < nrows; row += nwarps) {
        float2 xv = *(const float2*)&in[(size_t)row * 64 + 2 * lane];
        float y0 = fmaf(xv.y, w0b, xv.x * w0a);
        float y1 = fmaf(xv.y, w1b, xv.x * w1a);
#pragma unroll
        for (int o = 16; o > 0; o >>= 1) {
            y0 += __shfl_xor_sync(0xFFFFFFFFu, y0, o);
            y1 += __shfl_xor_sync(0xFFFFFFFFu, y1, o);
        }
        if (lane == 0) {
            float2 r;
            r.x = tanh_fast(y0 + b0);
            r.y = tanh_fast(y1 + b1);
            *(float2*)&outp[(size_t)row * 2] = r;
        }
    }
}

// ---------------------------------------------------------------------------
extern "C" void kernel_launch(void* const* d_in, const int* in_sizes, int n_in,
                              void* d_out, int out_size)
{
    const float* x    = (const float*)d_in[0];
    const float* Wih0 = (const float*)d_in[1];
    const float* Whh0 = (const float*)d_in[2];
    const float* bih0 = (const float*)d_in[3];
    const float* bhh0 = (const float*)d_in[4];
    const float* Wih  = (const float*)d_in[5];
    const float* Whh  = (const float*)d_in[6];
    const float* bih  = (const float*)d_in[7];
    const float* bhh  = (const float*)d_in[8];
    const float* Wfc  = (const float*)d_in[9];
    const float* bfc  = (const float*)d_in[10];
    float* out = (float*)d_out;

    const int MB = (BB * TT) / 64;  // GEMM grid.x

    // Layer 0 -> buf0
    gru_l0<<<dim3(BB / 4, 2), 128>>>(x, Wih0, Whh0, bih0, bhh0);
    // Layer 1: buf0 -> xg -> buf1
    xgemm_mma<<<dim3(MB, 2), 256>>>(0, Wih, bih);
    gru_rec<<<dim3(BB / 4, 2), 128>>>(1, Whh, bhh);
    // Layer 2: buf1 -> xg -> buf0
    xgemm_mma<<<dim3(MB, 2), 256>>>(1, Wih + 192 * 64, bih + 192);
    gru_rec<<<dim3(BB / 4, 2), 128>>>(0, Whh + 192 * 32, bhh + 192);
    // FC
    fc_kernel<<<2048, 256>>>(Wfc, bfc, out);
}

// round 8
// speedup vs baseline: 1.6102x; 1.0677x over previous
#include <cuda_runtime.h>
#include <cuda_bf16.h>

#define BB 16384
#define TT 64

// Ping-pong layer buffers: [B][T][64] (fwd in [0:32), bwd in [32:64))
__device__ float g_buf0[BB * TT * 64];
__device__ float g_buf1[BB * TT * 64];

__device__ __forceinline__ float sigf(float x) {
    return __fdividef(1.0f, 1.0f + __expf(-x));
}
__device__ __forceinline__ float tanh_fast(float x) {
    float e = __expf(-2.0f * x);
    return __fdividef(1.0f - e, 1.0f + e);
}

__device__ __forceinline__ void mma16816(float* c, const unsigned* a,
                                         unsigned b0, unsigned b1) {
    asm volatile(
        "mma.sync.aligned.m16n8k16.row.col.f32.bf16.bf16.f32 "
        "{%0,%1,%2,%3}, {%4,%5,%6,%7}, {%8,%9}, {%0,%1,%2,%3};"
        : "+f"(c[0]), "+f"(c[1]), "+f"(c[2]), "+f"(c[3])
        : "r"(a[0]), "r"(a[1]), "r"(a[2]), "r"(a[3]), "r"(b0), "r"(b1));
}
__device__ __forceinline__ void ldsm4(unsigned* r, unsigned addr) {
    asm volatile(
        "ldmatrix.sync.aligned.m8n8.x4.shared.b16 {%0,%1,%2,%3}, [%4];"
        : "=r"(r[0]), "=r"(r[1]), "=r"(r[2]), "=r"(r[3]) : "r"(addr));
}
// 3-pass Markidis accumulate: c += Ahi*Bhi + Ahi*Blo + Alo*Bhi
__device__ __forceinline__ void mma3(float* c, const unsigned* ah, const unsigned* al,
                                     unsigned bh0, unsigned bh1,
                                     unsigned bl0, unsigned bl1) {
    mma16816(c, ah, bh0, bh1);
    mma16816(c, ah, bl0, bl1);
    mma16816(c, al, bh0, bh1);
}
// Split two floats into packed bf16x2 hi / lo residual pairs.
__device__ __forceinline__ void split2(float a, float b, unsigned& hi, unsigned& lo) {
    __nv_bfloat16 ah = __float2bfloat16(a), bh = __float2bfloat16(b);
    __nv_bfloat16 al = __float2bfloat16(a - __bfloat162float(ah));
    __nv_bfloat16 bl = __float2bfloat16(b - __bfloat162float(bh));
    __nv_bfloat162 ph(ah, bh), pl(al, bl);
    hi = *(unsigned*)&ph; lo = *(unsigned*)&pl;
}

// ---------------------------------------------------------------------------
// Layer 0: input K=2. One warp per (batch, dir). (unchanged)
// ---------------------------------------------------------------------------
__global__ __launch_bounds__(128) void gru_l0(
    const float* __restrict__ x,
    const float* __restrict__ Wih0, const float* __restrict__ Whh0,
    const float* __restrict__ bih0, const float* __restrict__ bhh0)
{
    const int w = threadIdx.x >> 5, lane = threadIdx.x & 31;
    const int b = blockIdx.x * 4 + w;
    const int dir = blockIdx.y;

    __shared__ __align__(16) float hb[4][2][32];
    __shared__ __align__(16) float xs[4][128];

    const float* wi = Wih0 + dir * 96 * 2;
    const float* wh = Whh0 + dir * 96 * 32;
    const float* bi = bih0 + dir * 96;
    const float* bh = bhh0 + dir * 96;

    {
        float4 v = *(const float4*)(x + (size_t)b * 128 + lane * 4);
        *(float4*)&xs[w][lane * 4] = v;
    }

    const float wx0 = wi[(lane) * 2 + 0],      wx1 = wi[(lane) * 2 + 1];
    const float wz0 = wi[(32 + lane) * 2 + 0], wz1 = wi[(32 + lane) * 2 + 1];
    const float wn0 = wi[(64 + lane) * 2 + 0], wn1 = wi[(64 + lane) * 2 + 1];

    float whr[32], whz[32], whn[32];
#pragma unroll
    for (int k = 0; k < 32; k += 4) {
        float4 a = *(const float4*)&wh[(lane) * 32 + k];
        whr[k] = a.x; whr[k + 1] = a.y; whr[k + 2] = a.z; whr[k + 3] = a.w;
        float4 c = *(const float4*)&wh[(32 + lane) * 32 + k];
        whz[k] = c.x; whz[k + 1] = c.y; whz[k + 2] = c.z; whz[k + 3] = c.w;
        float4 d = *(const float4*)&wh[(64 + lane) * 32 + k];
        whn[k] = d.x; whn[k + 1] = d.y; whn[k + 2] = d.z; whn[k + 3] = d.w;
    }
    const float br  = bi[lane] + bh[lane];
    const float bz  = bi[32 + lane] + bh[32 + lane];
    const float bxn = bi[64 + lane];
    const float bhn = bh[64 + lane];

    float h = 0.0f;
    hb[w][0][lane] = 0.0f;
    __syncwarp();

    float* outp = g_buf0 + (size_t)b * TT * 64 + dir * 32 + lane;

    for (int t = 0; t < TT; t++) {
        const int te = dir ? (TT - 1 - t) : t;
        const float x0 = xs[w][te * 2 + 0];
        const float x1 = xs[w][te * 2 + 1];

        float sr0 = fmaf(x1, wx1, fmaf(x0, wx0, br)),  sr1 = 0.f;
        float sz0 = fmaf(x1, wz1, fmaf(x0, wz0, bz)),  sz1 = 0.f;
        float sn0 = bhn, sn1 = 0.f;

        const float4* h4 = (const float4*)hb[w][t & 1];
#pragma unroll
        for (int c = 0; c < 8; c++) {
            float4 v = h4[c];
            sr0 = fmaf(v.x, whr[4 * c + 0], sr0);
            sr0 = fmaf(v.y, whr[4 * c + 1], sr0);
            sr1 = fmaf(v.z, whr[4 * c + 2], sr1);
            sr1 = fmaf(v.w, whr[4 * c + 3], sr1);
            sz0 = fmaf(v.x, whz[4 * c + 0], sz0);
            sz0 = fmaf(v.y, whz[4 * c + 1], sz0);
            sz1 = fmaf(v.z, whz[4 * c + 2], sz1);
            sz1 = fmaf(v.w, whz[4 * c + 3], sz1);
            sn0 = fmaf(v.x, whn[4 * c + 0], sn0);
            sn0 = fmaf(v.y, whn[4 * c + 1], sn0);
            sn1 = fmaf(v.z, whn[4 * c + 2], sn1);
            sn1 = fmaf(v.w, whn[4 * c + 3], sn1);
        }
        const float r = sigf(sr0 + sr1);
        const float z = sigf(sz0 + sz1);
        const float n = tanh_fast(fmaf(r, sn0 + sn1, fmaf(x1, wn1, fmaf(x0, wn0, bxn))));
        h = fmaf(z, h - n, n);

        hb[w][(t + 1) & 1][lane] = h;
        outp[(size_t)te * 64] = h;
        __syncwarp();
    }
}

// ---------------------------------------------------------------------------
// Fused tensor-core GRU layer (layers 1/2): per-step mma for BOTH the input
// GEMM (K=64) and the recurrent GEMM (K=32), bf16 3-pass Markidis split,
// fp32 accumulators initialized from biases each step. No xg buffer.
// Block = 64 batches x 1 dir x all 64 steps; 8 warps; warp = 16 rows x
// (2 jgroups x 3 gates) n-tiles. One __syncthreads per step.
// ---------------------------------------------------------------------------
#define XELEMS (64 * 72)      // one X buffer (bf16 elems)
#define HELEMS (64 * 40)
#define SMEM_FUSED ((2*XELEMS*2 + 2*96*72 + 2*96*40 + 2*HELEMS*2) * 2)  // bytes

__global__ __launch_bounds__(256, 2) void gru_fused(
    int phase,
    const float* __restrict__ Wih_l,  // [2][96][64] this layer
    const float* __restrict__ Whh_l,  // [2][96][32]
    const float* __restrict__ bih_l,  // [2][96]
    const float* __restrict__ bhh_l)  // [2][96]
{
    const float* in  = phase ? g_buf1 : g_buf0;
    float*       out = phase ? g_buf0 : g_buf1;
    const int dir = blockIdx.y;
    const size_t b0 = (size_t)blockIdx.x * 64;

    extern __shared__ __align__(16) __nv_bfloat16 sm[];
    __nv_bfloat16* Xhi = sm;                      // [2][64][72]
    __nv_bfloat16* Xlo = Xhi + 2 * XELEMS;
    __nv_bfloat16* Wsh = Xlo + 2 * XELEMS;        // [96][72]
    __nv_bfloat16* Wsl = Wsh + 96 * 72;
    __nv_bfloat16* Ush = Wsl + 96 * 72;           // [96][40]
    __nv_bfloat16* Usl = Ush + 96 * 40;
    __nv_bfloat16* Hh  = Usl + 96 * 40;           // [2][64][40]
    __nv_bfloat16* Hl  = Hh + 2 * HELEMS;

    const int tid = threadIdx.x;
    const float* Wi = Wih_l + (size_t)dir * 96 * 64;
    const float* Wh = Whh_l + (size_t)dir * 96 * 32;
    const float* bi = bih_l + dir * 96;
    const float* bh = bhh_l + dir * 96;

    // ---- Stage weights (split hi/lo) ----
    for (int q = tid; q < 96 * 16; q += 256) {
        const int gr = q >> 4, k4 = (q & 15) << 2;
        float4 v = *(const float4*)&Wi[gr * 64 + k4];
        unsigned h0, l0, h1, l1;
        split2(v.x, v.y, h0, l0);
        split2(v.z, v.w, h1, l1);
        *(unsigned*)&Wsh[gr * 72 + k4]     = h0;
        *(unsigned*)&Wsh[gr * 72 + k4 + 2] = h1;
        *(unsigned*)&Wsl[gr * 72 + k4]     = l0;
        *(unsigned*)&Wsl[gr * 72 + k4 + 2] = l1;
    }
    for (int q = tid; q < 96 * 8; q += 256) {
        const int gr = q >> 3, k4 = (q & 7) << 2;
        float4 v = *(const float4*)&Wh[gr * 32 + k4];
        unsigned h0, l0, h1, l1;
        split2(v.x, v.y, h0, l0);
        split2(v.z, v.w, h1, l1);
        *(unsigned*)&Ush[gr * 40 + k4]     = h0;
        *(unsigned*)&Ush[gr * 40 + k4 + 2] = h1;
        *(unsigned*)&Usl[gr * 40 + k4]     = l0;
        *(unsigned*)&Usl[gr * 40 + k4 + 2] = l1;
    }
    for (int q = tid; q < 2 * HELEMS / 2; q += 256) {
        ((unsigned*)Hh)[q] = 0u;
        ((unsigned*)Hl)[q] = 0u;
    }

    // ---- Thread geometry ----
    const int wid = tid >> 5, lane = tid & 31;
    const int mrow0 = (wid & 3) << 4;   // m-tile rows
    const int pair  = wid >> 2;         // jgroup pair: units [pair*16, pair*16+16)
    const int g  = lane >> 2;
    const int t2 = (lane & 3) << 1;

    // Bias registers (per thread cols).
    float bias_r[2][2], bias_z[2][2], bias_xn[2][2], bias_hn[2][2];
#pragma unroll
    for (int J = 0; J < 2; J++) {
        const int u = (pair * 2 + J) * 8 + t2;
#pragma unroll
        for (int c = 0; c < 2; c++) {
            bias_r[J][c]  = bi[u + c]      + bh[u + c];
            bias_z[J][c]  = bi[32 + u + c] + bh[32 + u + c];
            bias_xn[J][c] = bi[64 + u + c];
            bias_hn[J][c] = bh[64 + u + c];
        }
    }

    // ldmatrix addresses.
    const int a_r = lane & 15, a_k = (lane >> 4) << 3;
    const unsigned xAhi = (unsigned)__cvta_generic_to_shared(&Xhi[(mrow0 + a_r) * 72 + a_k]);
    const unsigned xAlo = (unsigned)__cvta_generic_to_shared(&Xlo[(mrow0 + a_r) * 72 + a_k]);
    const unsigned hAhi = (unsigned)__cvta_generic_to_shared(&Hh[(mrow0 + a_r) * 40 + a_k]);
    const unsigned hAlo = (unsigned)__cvta_generic_to_shared(&Hl[(mrow0 + a_r) * 40 + a_k]);
    const int w_jj = (lane >> 4) & 1, w_kh = ((lane >> 3) & 1) << 3;
    unsigned wBhi_[3], wBlo_[3], uBhi_[3], uBlo_[3];
#pragma unroll
    for (int gt = 0; gt < 3; gt++) {
        const int row = gt * 32 + pair * 16 + w_jj * 8 + (lane & 7);
        wBhi_[gt] = (unsigned)__cvta_generic_to_shared(&Wsh[row * 72 + w_kh]);
        wBlo_[gt] = (unsigned)__cvta_generic_to_shared(&Wsl[row * 72 + w_kh]);
        uBhi_[gt] = (unsigned)__cvta_generic_to_shared(&Ush[row * 40 + w_kh]);
        uBlo_[gt] = (unsigned)__cvta_generic_to_shared(&Usl[row * 40 + w_kh]);
    }
    const unsigned XBUF = XELEMS * 2;  // bytes
    const unsigned HBUF = HELEMS * 2;

    // ---- x prefetch (this thread: row tid>>2, cols (tid&3)*16 .. +15) ----
    const float* xrow = in + (b0 + (tid >> 2)) * 4096 + ((tid & 3) << 4);
    float4 px[4];
    __nv_bfloat16* xdh = Xhi + (tid >> 2) * 72 + ((tid & 3) << 4);
    __nv_bfloat16* xdl = Xlo + (tid >> 2) * 72 + ((tid & 3) << 4);

    auto store_x = [&](int nb) {
        uint4 hv, lv;
        split2(px[0].x, px[0].y, hv.x, lv.x);
        split2(px[0].z, px[0].w, hv.y, lv.y);
        split2(px[1].x, px[1].y, hv.z, lv.z);
        split2(px[1].z, px[1].w, hv.w, lv.w);
        *(uint4*)(xdh + nb * XELEMS) = hv;
        *(uint4*)(xdl + nb * XELEMS) = lv;
        split2(px[2].x, px[2].y, hv.x, lv.x);
        split2(px[2].z, px[2].w, hv.y, lv.y);
        split2(px[3].x, px[3].y, hv.z, lv.z);
        split2(px[3].z, px[3].w, hv.w, lv.w);
        *(uint4*)(xdh + nb * XELEMS + 8) = hv;
        *(uint4*)(xdl + nb * XELEMS + 8) = lv;
    };

    {
        const int te0 = dir ? (TT - 1) : 0;
#pragma unroll
        for (int i = 0; i < 4; i++) px[i] = *(const float4*)(xrow + te0 * 64 + i * 4);
        store_x(0);
        const int te1 = dir ? (TT - 2) : 1;
#pragma unroll
        for (int i = 0; i < 4; i++) px[i] = *(const float4*)(xrow + te1 * 64 + i * 4);
    }
    __syncthreads();

    float hp[2][4];
#pragma unroll
    for (int J = 0; J < 2; J++)
#pragma unroll
        for (int q = 0; q < 4; q++) hp[J][q] = 0.0f;

    // ---- Main time loop ----
    for (int t = 0; t < TT; t++) {
        const int buf = t & 1, nbuf = buf ^ 1;
        const int te = dir ? (TT - 1 - t) : t;

        // Convert x_{t+1} into X[nbuf]; prefetch x_{t+2}.
        if (t + 1 < TT) {
            store_x(nbuf);
            if (t + 2 < TT) {
                const int te2 = dir ? (TT - 3 - t) : (t + 2);
#pragma unroll
                for (int i = 0; i < 4; i++)
                    px[i] = *(const float4*)(xrow + te2 * 64 + i * 4);
            }
        }

        // Init accumulators from bias.
        float accr[2][4], accz[2][4], accxn[2][4], acchn[2][4];
#pragma unroll
        for (int J = 0; J < 2; J++) {
            accr[J][0] = bias_r[J][0];  accr[J][1] = bias_r[J][1];
            accr[J][2] = bias_r[J][0];  accr[J][3] = bias_r[J][1];
            accz[J][0] = bias_z[J][0];  accz[J][1] = bias_z[J][1];
            accz[J][2] = bias_z[J][0];  accz[J][3] = bias_z[J][1];
            accxn[J][0] = bias_xn[J][0]; accxn[J][1] = bias_xn[J][1];
            accxn[J][2] = bias_xn[J][0]; accxn[J][3] = bias_xn[J][1];
            acchn[J][0] = bias_hn[J][0]; acchn[J][1] = bias_hn[J][1];
            acchn[J][2] = bias_hn[J][0]; acchn[J][3] = bias_hn[J][1];
        }

        // xgate mma: A = X[buf], K=64 (4 chunks).
        const unsigned xoff = buf * XBUF;
#pragma unroll
        for (int ks = 0; ks < 4; ks++) {
            const unsigned ko = ks * 32;
            unsigned ah[4], al[4], bhf[4], blf[4];
            ldsm4(ah, xAhi + xoff + ko);
            ldsm4(al, xAlo + xoff + ko);
            ldsm4(bhf, wBhi_[0] + ko); ldsm4(blf, wBlo_[0] + ko);
            mma3(accr[0], ah, al, bhf[0], bhf[1], blf[0], blf[1]);
            mma3(accr[1], ah, al, bhf[2], bhf[3], blf[2], blf[3]);
            ldsm4(bhf, wBhi_[1] + ko); ldsm4(blf, wBlo_[1] + ko);
            mma3(accz[0], ah, al, bhf[0], bhf[1], blf[0], blf[1]);
            mma3(accz[1], ah, al, bhf[2], bhf[3], blf[2], blf[3]);
            ldsm4(bhf, wBhi_[2] + ko); ldsm4(blf, wBlo_[2] + ko);
            mma3(accxn[0], ah, al, bhf[0], bhf[1], blf[0], blf[1]);
            mma3(accxn[1], ah, al, bhf[2], bhf[3], blf[2], blf[3]);
        }

        // hgate mma: A = H[buf], K=32 (2 chunks).
        const unsigned hoff = buf * HBUF;
#pragma unroll
        for (int ks = 0; ks < 2; ks++) {
            const unsigned ko = ks * 32;
            unsigned ah[4], al[4], bhf[4], blf[4];
            ldsm4(ah, hAhi + hoff + ko);
            ldsm4(al, hAlo + hoff + ko);
            ldsm4(bhf, uBhi_[0] + ko); ldsm4(blf, uBlo_[0] + ko);
            mma3(accr[0], ah, al, bhf[0], bhf[1], blf[0], blf[1]);
            mma3(accr[1], ah, al, bhf[2], bhf[3], blf[2], blf[3]);
            ldsm4(bhf, uBhi_[1] + ko); ldsm4(blf, uBlo_[1] + ko);
            mma3(accz[0], ah, al, bhf[0], bhf[1], blf[0], blf[1]);
            mma3(accz[1], ah, al, bhf[2], bhf[3], blf[2], blf[3]);
            ldsm4(bhf, uBhi_[2] + ko); ldsm4(blf, uBlo_[2] + ko);
            mma3(acchn[0], ah, al, bhf[0], bhf[1], blf[0], blf[1]);
            mma3(acchn[1], ah, al, bhf[2], bhf[3], blf[2], blf[3]);
        }

        // Activations, h update, store.
#pragma unroll
        for (int J = 0; J < 2; J++) {
            float hh[4];
#pragma unroll
            for (int q = 0; q < 4; q++) {
                const float r = sigf(accr[J][q]);
                const float z = sigf(accz[J][q]);
                const float n = tanh_fast(fmaf(r, acchn[J][q], accxn[J][q]));
                hh[q] = fmaf(z, hp[J][q] - n, n);
                hp[J][q] = hh[q];
            }
            const int u = (pair * 2 + J) * 8 + t2;
            unsigned hi01, lo01, hi23, lo23;
            split2(hh[0], hh[1], hi01, lo01);
            split2(hh[2], hh[3], hi23, lo23);
            const int hb = nbuf * HELEMS;
            *(unsigned*)&Hh[hb + (mrow0 + g) * 40 + u]     = hi01;
            *(unsigned*)&Hl[hb + (mrow0 + g) * 40 + u]     = lo01;
            *(unsigned*)&Hh[hb + (mrow0 + g + 8) * 40 + u] = hi23;
            *(unsigned*)&Hl[hb + (mrow0 + g + 8) * 40 + u] = lo23;

            float2 o01; o01.x = hh[0]; o01.y = hh[1];
            float2 o23; o23.x = hh[2]; o23.y = hh[3];
            *(float2*)&out[(b0 + mrow0 + g) * 4096 + (size_t)te * 64 + dir * 32 + u] = o01;
            *(float2*)&out[(b0 + mrow0 + g + 8) * 4096 + (size_t)te * 64 + dir * 32 + u] = o23;
        }
        __syncthreads();
    }
}

// ---------------------------------------------------------------------------
// Final FC: y = tanh(out @ Wfc.T + bfc). Warp per row, shuffle reduction.
// ---------------------------------------------------------------------------
__global__ __launch_bounds__(256) void fc_kernel(
    const float* __restrict__ Wfc, const float* __restrict__ bfc,
    float* __restrict__ outp)
{
    const float* in = g_buf0;  // layer 2 output
    const int lane = threadIdx.x & 31;
    const int warp = (blockIdx.x * blockDim.x + threadIdx.x) >> 5;
    const int nwarps = (gridDim.x * blockDim.x) >> 5;

    const float w0a = __ldg(&Wfc[2 * lane]),      w0b = __ldg(&Wfc[2 * lane + 1]);
    const float w1a = __ldg(&Wfc[64 + 2 * lane]), w1b = __ldg(&Wfc[64 + 2 * lane + 1]);
    const float b0 = __ldg(&bfc[0]), b1 = __ldg(&bfc[1]);

    const int nrows = BB * TT;
    for (int row = warp; row < nrows; row += nwarps) {
        float2 xv = *(const float2*)&in[(size_t)row * 64 + 2 * lane];
        float y0 = fmaf(xv.y, w0b, xv.x * w0a);
        float y1 = fmaf(xv.y, w1b, xv.x * w1a);
#pragma unroll
        for (int o = 16; o > 0; o >>= 1) {
            y0 += __shfl_xor_sync(0xFFFFFFFFu, y0, o);
            y1 += __shfl_xor_sync(0xFFFFFFFFu, y1, o);
        }
        if (lane == 0) {
            float2 r;
            r.x = tanh_fast(y0 + b0);
            r.y = tanh_fast(y1 + b1);
            *(float2*)&outp[(size_t)row * 2] = r;
        }
    }
}

// ---------------------------------------------------------------------------
extern "C" void kernel_launch(void* const* d_in, const int* in_sizes, int n_in,
                              void* d_out, int out_size)
{
    const float* x    = (const float*)d_in[0];
    const float* Wih0 = (const float*)d_in[1];
    const float* Whh0 = (const float*)d_in[2];
    const float* bih0 = (const float*)d_in[3];
    const float* bhh0 = (const float*)d_in[4];
    const float* Wih  = (const float*)d_in[5];
    const float* Whh  = (const float*)d_in[6];
    const float* bih  = (const float*)d_in[7];
    const float* bhh  = (const float*)d_in[8];
    const float* Wfc  = (const float*)d_in[9];
    const float* bfc  = (const float*)d_in[10];
    float* out = (float*)d_out;

    // Opt in to >48KB dynamic smem (attribute set; not a stream op, capture-safe).
    cudaFuncSetAttribute(gru_fused, cudaFuncAttributeMaxDynamicSharedMemorySize,
                         SMEM_FUSED);

    // Layer 0 -> buf0
    gru_l0<<<dim3(BB / 4, 2), 128>>>(x, Wih0, Whh0, bih0, bhh0);
    // Layer 1: buf0 -> buf1 (fused)
    gru_fused<<<dim3(BB / 64, 2), 256, SMEM_FUSED>>>(0, Wih, Whh, bih, bhh);
    // Layer 2: buf1 -> buf0 (fused)
    gru_fused<<<dim3(BB / 64, 2), 256, SMEM_FUSED>>>(
        1, Wih + 2 * 96 * 64, Whh + 2 * 96 * 32, bih + 2 * 96, bhh + 2 * 96);
    // FC
    fc_kernel<<<2048, 256>>>(Wfc, bfc, out);
}

// round 9
// speedup vs baseline: 2.5731x; 1.5980x over previous
#include <cuda_runtime.h>
#include <cuda_bf16.h>

#define BB 16384
#define TT 64

// Ping-pong layer buffers: [B][T][64] (fwd in [0:32), bwd in [32:64))
__device__ float g_buf0[BB * TT * 64];
__device__ float g_buf1[BB * TT * 64];

__device__ __forceinline__ float sigf(float x) {
    return __fdividef(1.0f, 1.0f + __expf(-x));
}
__device__ __forceinline__ float tanh_fast(float x) {
    float e = __expf(-2.0f * x);
    return __fdividef(1.0f - e, 1.0f + e);
}

__device__ __forceinline__ void mma16816(float* c, const unsigned* a,
                                         unsigned b0, unsigned b1) {
    asm volatile(
        "mma.sync.aligned.m16n8k16.row.col.f32.bf16.bf16.f32 "
        "{%0,%1,%2,%3}, {%4,%5,%6,%7}, {%8,%9}, {%0,%1,%2,%3};"
        : "+f"(c[0]), "+f"(c[1]), "+f"(c[2]), "+f"(c[3])
        : "r"(a[0]), "r"(a[1]), "r"(a[2]), "r"(a[3]), "r"(b0), "r"(b1));
}
__device__ __forceinline__ void ldsm4(unsigned* r, unsigned addr) {
    asm volatile(
        "ldmatrix.sync.aligned.m8n8.x4.shared.b16 {%0,%1,%2,%3}, [%4];"
        : "=r"(r[0]), "=r"(r[1]), "=r"(r[2]), "=r"(r[3]) : "r"(addr));
}
__device__ __forceinline__ void ldsm2(unsigned* r, unsigned addr) {
    asm volatile(
        "ldmatrix.sync.aligned.m8n8.x2.shared.b16 {%0,%1}, [%2];"
        : "=r"(r[0]), "=r"(r[1]) : "r"(addr));
}
// 3-pass Markidis accumulate: c += Ahi*Bhi + Ahi*Blo + Alo*Bhi
__device__ __forceinline__ void mma3(float* c, const unsigned* ah, const unsigned* al,
                                     unsigned bh0, unsigned bh1,
                                     unsigned bl0, unsigned bl1) {
    mma16816(c, ah, bh0, bh1);
    mma16816(c, ah, bl0, bl1);
    mma16816(c, al, bh0, bh1);
}
// Split two floats into packed bf16x2 hi / lo residual pairs.
__device__ __forceinline__ void split2(float a, float b, unsigned& hi, unsigned& lo) {
    __nv_bfloat16 ah = __float2bfloat16(a), bh = __float2bfloat16(b);
    __nv_bfloat16 al = __float2bfloat16(a - __bfloat162float(ah));
    __nv_bfloat16 bl = __float2bfloat16(b - __bfloat162float(bh));
    __nv_bfloat162 ph(ah, bh), pl(al, bl);
    hi = *(unsigned*)&ph; lo = *(unsigned*)&pl;
}

// ---------------------------------------------------------------------------
// Layer 0: input K=2. One warp per (batch, dir). (unchanged)
// ---------------------------------------------------------------------------
__global__ __launch_bounds__(128) void gru_l0(
    const float* __restrict__ x,
    const float* __restrict__ Wih0, const float* __restrict__ Whh0,
    const float* __restrict__ bih0, const float* __restrict__ bhh0)
{
    const int w = threadIdx.x >> 5, lane = threadIdx.x & 31;
    const int b = blockIdx.x * 4 + w;
    const int dir = blockIdx.y;

    __shared__ __align__(16) float hb[4][2][32];
    __shared__ __align__(16) float xs[4][128];

    const float* wi = Wih0 + dir * 96 * 2;
    const float* wh = Whh0 + dir * 96 * 32;
    const float* bi = bih0 + dir * 96;
    const float* bh = bhh0 + dir * 96;

    {
        float4 v = *(const float4*)(x + (size_t)b * 128 + lane * 4);
        *(float4*)&xs[w][lane * 4] = v;
    }

    const float wx0 = wi[(lane) * 2 + 0],      wx1 = wi[(lane) * 2 + 1];
    const float wz0 = wi[(32 + lane) * 2 + 0], wz1 = wi[(32 + lane) * 2 + 1];
    const float wn0 = wi[(64 + lane) * 2 + 0], wn1 = wi[(64 + lane) * 2 + 1];

    float whr[32], whz[32], whn[32];
#pragma unroll
    for (int k = 0; k < 32; k += 4) {
        float4 a = *(const float4*)&wh[(lane) * 32 + k];
        whr[k] = a.x; whr[k + 1] = a.y; whr[k + 2] = a.z; whr[k + 3] = a.w;
        float4 c = *(const float4*)&wh[(32 + lane) * 32 + k];
        whz[k] = c.x; whz[k + 1] = c.y; whz[k + 2] = c.z; whz[k + 3] = c.w;
        float4 d = *(const float4*)&wh[(64 + lane) * 32 + k];
        whn[k] = d.x; whn[k + 1] = d.y; whn[k + 2] = d.z; whn[k + 3] = d.w;
    }
    const float br  = bi[lane] + bh[lane];
    const float bz  = bi[32 + lane] + bh[32 + lane];
    const float bxn = bi[64 + lane];
    const float bhn = bh[64 + lane];

    float h = 0.0f;
    hb[w][0][lane] = 0.0f;
    __syncwarp();

    float* outp = g_buf0 + (size_t)b * TT * 64 + dir * 32 + lane;

    for (int t = 0; t < TT; t++) {
        const int te = dir ? (TT - 1 - t) : t;
        const float x0 = xs[w][te * 2 + 0];
        const float x1 = xs[w][te * 2 + 1];

        float sr0 = fmaf(x1, wx1, fmaf(x0, wx0, br)),  sr1 = 0.f;
        float sz0 = fmaf(x1, wz1, fmaf(x0, wz0, bz)),  sz1 = 0.f;
        float sn0 = bhn, sn1 = 0.f;

        const float4* h4 = (const float4*)hb[w][t & 1];
#pragma unroll
        for (int c = 0; c < 8; c++) {
            float4 v = h4[c];
            sr0 = fmaf(v.x, whr[4 * c + 0], sr0);
            sr0 = fmaf(v.y, whr[4 * c + 1], sr0);
            sr1 = fmaf(v.z, whr[4 * c + 2], sr1);
            sr1 = fmaf(v.w, whr[4 * c + 3], sr1);
            sz0 = fmaf(v.x, whz[4 * c + 0], sz0);
            sz0 = fmaf(v.y, whz[4 * c + 1], sz0);
            sz1 = fmaf(v.z, whz[4 * c + 2], sz1);
            sz1 = fmaf(v.w, whz[4 * c + 3], sz1);
            sn0 = fmaf(v.x, whn[4 * c + 0], sn0);
            sn0 = fmaf(v.y, whn[4 * c + 1], sn0);
            sn1 = fmaf(v.z, whn[4 * c + 2], sn1);
            sn1 = fmaf(v.w, whn[4 * c + 3], sn1);
        }
        const float r = sigf(sr0 + sr1);
        const float z = sigf(sz0 + sz1);
        const float n = tanh_fast(fmaf(r, sn0 + sn1, fmaf(x1, wn1, fmaf(x0, wn0, bxn))));
        h = fmaf(z, h - n, n);

        hb[w][(t + 1) & 1][lane] = h;
        outp[(size_t)te * 64] = h;
        __syncwarp();
    }
}

// ---------------------------------------------------------------------------
// Fused tensor-core GRU layer (layers 1/2), v2:
// 512 threads = 16 warps; warp = (mtile 0..3, unit-group 0..3).
// Each 128-thread mtile GROUP is independent after weight staging (own X rows,
// own H rows, shared read-only W) -> per-step sync is bar.sync(8+mtile, 128),
// groups drift freely. 54 mma/warp/step (B via ldmatrix.x2).
// ---------------------------------------------------------------------------
#define XELEMS (64 * 72)      // one X buffer (bf16 elems)
#define HELEMS (64 * 40)
#define SMEM_FUSED ((2*XELEMS*2 + 2*96*72 + 2*96*40 + 2*HELEMS*2) * 2)  // bytes

__global__ __launch_bounds__(512, 2) void gru_fused(
    int phase,
    const float* __restrict__ Wih_l,  // [2][96][64] this layer
    const float* __restrict__ Whh_l,  // [2][96][32]
    const float* __restrict__ bih_l,  // [2][96]
    const float* __restrict__ bhh_l)  // [2][96]
{
    const float* in  = phase ? g_buf1 : g_buf0;
    float*       out = phase ? g_buf0 : g_buf1;
    const int dir = blockIdx.y;
    const size_t b0 = (size_t)blockIdx.x * 64;

    extern __shared__ __align__(16) __nv_bfloat16 sm[];
    __nv_bfloat16* Xhi = sm;                      // [2][64][72]
    __nv_bfloat16* Xlo = Xhi + 2 * XELEMS;
    __nv_bfloat16* Wsh = Xlo + 2 * XELEMS;        // [96][72]
    __nv_bfloat16* Wsl = Wsh + 96 * 72;
    __nv_bfloat16* Ush = Wsl + 96 * 72;           // [96][40]
    __nv_bfloat16* Usl = Ush + 96 * 40;
    __nv_bfloat16* Hh  = Usl + 96 * 40;           // [2][64][40]
    __nv_bfloat16* Hl  = Hh + 2 * HELEMS;

    const int tid = threadIdx.x;
    const float* Wi = Wih_l + (size_t)dir * 96 * 64;
    const float* Wh = Whh_l + (size_t)dir * 96 * 32;
    const float* bi = bih_l + dir * 96;
    const float* bh = bhh_l + dir * 96;

    // ---- Stage weights (split hi/lo), zero H ----
    for (int q = tid; q < 96 * 16; q += 512) {
        const int gr = q >> 4, k4 = (q & 15) << 2;
        float4 v = *(const float4*)&Wi[gr * 64 + k4];
        unsigned h0, l0, h1, l1;
        split2(v.x, v.y, h0, l0);
        split2(v.z, v.w, h1, l1);
        *(unsigned*)&Wsh[gr * 72 + k4]     = h0;
        *(unsigned*)&Wsh[gr * 72 + k4 + 2] = h1;
        *(unsigned*)&Wsl[gr * 72 + k4]     = l0;
        *(unsigned*)&Wsl[gr * 72 + k4 + 2] = l1;
    }
    for (int q = tid; q < 96 * 8; q += 512) {
        const int gr = q >> 3, k4 = (q & 7) << 2;
        float4 v = *(const float4*)&Wh[gr * 32 + k4];
        unsigned h0, l0, h1, l1;
        split2(v.x, v.y, h0, l0);
        split2(v.z, v.w, h1, l1);
        *(unsigned*)&Ush[gr * 40 + k4]     = h0;
        *(unsigned*)&Ush[gr * 40 + k4 + 2] = h1;
        *(unsigned*)&Usl[gr * 40 + k4]     = l0;
        *(unsigned*)&Usl[gr * 40 + k4 + 2] = l1;
    }
    for (int q = tid; q < 2 * HELEMS / 2; q += 512) {
        ((unsigned*)Hh)[q] = 0u;
        ((unsigned*)Hl)[q] = 0u;
    }

    // ---- Thread geometry ----
    const int wid = tid >> 5, lane = tid & 31;
    const int mtile = wid >> 2;         // 0..3, group id
    const int mrow0 = mtile << 4;       // batch rows [mrow0, mrow0+16)
    const int ug  = wid & 3;            // unit-group: units [ug*8, ug*8+8)
    const int u0  = ug << 3;
    const int g   = lane >> 2;
    const int t2  = (lane & 3) << 1;

    // Bias registers.
    const int ub = u0 + t2;
    float bias_r[2], bias_z[2], bias_xn[2], bias_hn[2];
#pragma unroll
    for (int c = 0; c < 2; c++) {
        bias_r[c]  = bi[ub + c]      + bh[ub + c];
        bias_z[c]  = bi[32 + ub + c] + bh[32 + ub + c];
        bias_xn[c] = bi[64 + ub + c];
        bias_hn[c] = bh[64 + ub + c];
    }

    // ldmatrix addresses.
    const int a_r = lane & 15, a_k = (lane >> 4) << 3;
    const unsigned xAhi = (unsigned)__cvta_generic_to_shared(&Xhi[(mrow0 + a_r) * 72 + a_k]);
    const unsigned xAlo = (unsigned)__cvta_generic_to_shared(&Xlo[(mrow0 + a_r) * 72 + a_k]);
    const unsigned hAhi = (unsigned)__cvta_generic_to_shared(&Hh[(mrow0 + a_r) * 40 + a_k]);
    const unsigned hAlo = (unsigned)__cvta_generic_to_shared(&Hl[(mrow0 + a_r) * 40 + a_k]);
    // B x2 for one n8 tile: lanes 0-7 -> (n8,k0), lanes 8-15 -> (n8,k8).
    const int b_row = (lane & 7), b_kh = ((lane >> 3) & 1) << 3;
    unsigned wBhi_[3], wBlo_[3], uBhi_[3], uBlo_[3];
#pragma unroll
    for (int gt = 0; gt < 3; gt++) {
        const int row = gt * 32 + u0 + b_row;
        wBhi_[gt] = (unsigned)__cvta_generic_to_shared(&Wsh[row * 72 + b_kh]);
        wBlo_[gt] = (unsigned)__cvta_generic_to_shared(&Wsl[row * 72 + b_kh]);
        uBhi_[gt] = (unsigned)__cvta_generic_to_shared(&Ush[row * 40 + b_kh]);
        uBlo_[gt] = (unsigned)__cvta_generic_to_shared(&Usl[row * 40 + b_kh]);
    }
    const unsigned XBUF = XELEMS * 2;  // bytes
    const unsigned HBUF = HELEMS * 2;

    // ---- x staging (group-local: 128 threads stage 16 rows x 64 cols) ----
    const int gtid = tid & 127;
    const int xr = mrow0 + (gtid >> 3);
    const int xc = (gtid & 7) << 3;      // 8 cols per thread
    const float* xrow = in + (b0 + xr) * 4096 + xc;
    __nv_bfloat16* xdh = Xhi + xr * 72 + xc;
    __nv_bfloat16* xdl = Xlo + xr * 72 + xc;
    float4 px[2];

    auto store_x = [&](int nb) {
        uint4 hv, lv;
        split2(px[0].x, px[0].y, hv.x, lv.x);
        split2(px[0].z, px[0].w, hv.y, lv.y);
        split2(px[1].x, px[1].y, hv.z, lv.z);
        split2(px[1].z, px[1].w, hv.w, lv.w);
        *(uint4*)(xdh + nb * XELEMS) = hv;
        *(uint4*)(xdl + nb * XELEMS) = lv;
    };

    {
        const int te0 = dir ? (TT - 1) : 0;
        px[0] = *(const float4*)(xrow + te0 * 64);
        px[1] = *(const float4*)(xrow + te0 * 64 + 4);
        store_x(0);
        const int te1 = dir ? (TT - 2) : 1;
        px[0] = *(const float4*)(xrow + te1 * 64);
        px[1] = *(const float4*)(xrow + te1 * 64 + 4);
    }
    __syncthreads();

    float hp[4] = {0.f, 0.f, 0.f, 0.f};
    const int barid = 8 + mtile;

    // ---- Main time loop (group-synchronous only) ----
    for (int t = 0; t < TT; t++) {
        const int buf = t & 1, nbuf = buf ^ 1;
        const int te = dir ? (TT - 1 - t) : t;

        // Convert x_{t+1} into X[nbuf]; prefetch x_{t+2}.
        if (t + 1 < TT) {
            store_x(nbuf);
            if (t + 2 < TT) {
                const int te2 = dir ? (TT - 3 - t) : (t + 2);
                px[0] = *(const float4*)(xrow + te2 * 64);
                px[1] = *(const float4*)(xrow + te2 * 64 + 4);
            }
        }

        // Init accumulators from bias.
        float accr[4], accz[4], accxn[4], acchn[4];
        accr[0] = bias_r[0];  accr[1] = bias_r[1];
        accr[2] = bias_r[0];  accr[3] = bias_r[1];
        accz[0] = bias_z[0];  accz[1] = bias_z[1];
        accz[2] = bias_z[0];  accz[3] = bias_z[1];
        accxn[0] = bias_xn[0]; accxn[1] = bias_xn[1];
        accxn[2] = bias_xn[0]; accxn[3] = bias_xn[1];
        acchn[0] = bias_hn[0]; acchn[1] = bias_hn[1];
        acchn[2] = bias_hn[0]; acchn[3] = bias_hn[1];

        // xgate mma: A = X[buf], K=64 (4 chunks).
        const unsigned xoff = buf * XBUF;
#pragma unroll
        for (int ks = 0; ks < 4; ks++) {
            const unsigned ko = ks * 32;
            unsigned ah[4], al[4], bh2[2], bl2[2];
            ldsm4(ah, xAhi + xoff + ko);
            ldsm4(al, xAlo + xoff + ko);
            ldsm2(bh2, wBhi_[0] + ko); ldsm2(bl2, wBlo_[0] + ko);
            mma3(accr, ah, al, bh2[0], bh2[1], bl2[0], bl2[1]);
            ldsm2(bh2, wBhi_[1] + ko); ldsm2(bl2, wBlo_[1] + ko);
            mma3(accz, ah, al, bh2[0], bh2[1], bl2[0], bl2[1]);
            ldsm2(bh2, wBhi_[2] + ko); ldsm2(bl2, wBlo_[2] + ko);
            mma3(accxn, ah, al, bh2[0], bh2[1], bl2[0], bl2[1]);
        }

        // hgate mma: A = H[buf], K=32 (2 chunks).
        const unsigned hoff = buf * HBUF;
#pragma unroll
        for (int ks = 0; ks < 2; ks++) {
            const unsigned ko = ks * 32;
            unsigned ah[4], al[4], bh2[2], bl2[2];
            ldsm4(ah, hAhi + hoff + ko);
            ldsm4(al, hAlo + hoff + ko);
            ldsm2(bh2, uBhi_[0] + ko); ldsm2(bl2, uBlo_[0] + ko);
            mma3(accr, ah, al, bh2[0], bh2[1], bl2[0], bl2[1]);
            ldsm2(bh2, uBhi_[1] + ko); ldsm2(bl2, uBlo_[1] + ko);
            mma3(accz, ah, al, bh2[0], bh2[1], bl2[0], bl2[1]);
            ldsm2(bh2, uBhi_[2] + ko); ldsm2(bl2, uBlo_[2] + ko);
            mma3(acchn, ah, al, bh2[0], bh2[1], bl2[0], bl2[1]);
        }

        // Activations, h update, stores.
        float hh[4];
#pragma unroll
        for (int q = 0; q < 4; q++) {
            const float r = sigf(accr[q]);
            const float z = sigf(accz[q]);
            const float n = tanh_fast(fmaf(r, acchn[q], accxn[q]));
            hh[q] = fmaf(z, hp[q] - n, n);
            hp[q] = hh[q];
        }
        unsigned hi01, lo01, hi23, lo23;
        split2(hh[0], hh[1], hi01, lo01);
        split2(hh[2], hh[3], hi23, lo23);
        const int hbo = nbuf * HELEMS;
        *(unsigned*)&Hh[hbo + (mrow0 + g) * 40 + ub]     = hi01;
        *(unsigned*)&Hl[hbo + (mrow0 + g) * 40 + ub]     = lo01;
        *(unsigned*)&Hh[hbo + (mrow0 + g + 8) * 40 + ub] = hi23;
        *(unsigned*)&Hl[hbo + (mrow0 + g + 8) * 40 + ub] = lo23;

        float2 o01; o01.x = hh[0]; o01.y = hh[1];
        float2 o23; o23.x = hh[2]; o23.y = hh[3];
        *(float2*)&out[(b0 + mrow0 + g) * 4096 + (size_t)te * 64 + dir * 32 + ub] = o01;
        *(float2*)&out[(b0 + mrow0 + g + 8) * 4096 + (size_t)te * 64 + dir * 32 + ub] = o23;

        asm volatile("bar.sync %0, %1;" :: "r"(barid), "r"(128) : "memory");
    }
}

// ---------------------------------------------------------------------------
// Final FC: y = tanh(out @ Wfc.T + bfc). Warp per row, shuffle reduction.
// ---------------------------------------------------------------------------
__global__ __launch_bounds__(256) void fc_kernel(
    const float* __restrict__ Wfc, const float* __restrict__ bfc,
    float* __restrict__ outp)
{
    const float* in = g_buf0;  // layer 2 output
    const int lane = threadIdx.x & 31;
    const int warp = (blockIdx.x * blockDim.x + threadIdx.x) >> 5;
    const int nwarps = (gridDim.x * blockDim.x) >> 5;

    const float w0a = __ldg(&Wfc[2 * lane]),      w0b = __ldg(&Wfc[2 * lane + 1]);
    const float w1a = __ldg(&Wfc[64 + 2 * lane]), w1b = __ldg(&Wfc[64 + 2 * lane + 1]);
    const float b0 = __ldg(&bfc[0]), b1 = __ldg(&bfc[1]);

    const int nrows = BB * TT;
    for (int row = warp; row < nrows; row += nwarps) {
        float2 xv = *(const float2*)&in[(size_t)row * 64 + 2 * lane];
        float y0 = fmaf(xv.y, w0b, xv.x * w0a);
        float y1 = fmaf(xv.y, w1b, xv.x * w1a);
#pragma unroll
        for (int o = 16; o > 0; o >>= 1) {
            y0 += __shfl_xor_sync(0xFFFFFFFFu, y0, o);
            y1 += __shfl_xor_sync(0xFFFFFFFFu, y1, o);
        }
        if (lane == 0) {
            float2 r;
            r.x = tanh_fast(y0 + b0);
            r.y = tanh_fast(y1 + b1);
            *(float2*)&outp[(size_t)row * 2] = r;
        }
    }
}

// ---------------------------------------------------------------------------
extern "C" void kernel_launch(void* const* d_in, const int* in_sizes, int n_in,
                              void* d_out, int out_size)
{
    const float* x    = (const float*)d_in[0];
    const float* Wih0 = (const float*)d_in[1];
    const float* Whh0 = (const float*)d_in[2];
    const float* bih0 = (const float*)d_in[3];
    const float* bhh0 = (const float*)d_in[4];
    const float* Wih  = (const float*)d_in[5];
    const float* Whh  = (const float*)d_in[6];
    const float* bih  = (const float*)d_in[7];
    const float* bhh  = (const float*)d_in[8];
    const float* Wfc  = (const float*)d_in[9];
    const float* bfc  = (const float*)d_in[10];
    float* out = (float*)d_out;

    cudaFuncSetAttribute(gru_fused, cudaFuncAttributeMaxDynamicSharedMemorySize,
                         SMEM_FUSED);

    // Layer 0 -> buf0
    gru_l0<<<dim3(BB / 4, 2), 128>>>(x, Wih0, Whh0, bih0, bhh0);
    // Layer 1: buf0 -> buf1 (fused)
    gru_fused<<<dim3(BB / 64, 2), 512, SMEM_FUSED>>>(0, Wih, Whh, bih, bhh);
    // Layer 2: buf1 -> buf0 (fused)
    gru_fused<<<dim3(BB / 64, 2), 512, SMEM_FUSED>>>(
        1, Wih + 2 * 96 * 64, Whh + 2 * 96 * 32, bih + 2 * 96, bhh + 2 * 96);
    // FC
    fc_kernel<<<2048, 256>>>(Wfc, bfc, out);
}

// round 10
// speedup vs baseline: 3.1231x; 1.2138x over previous
#include <cuda_runtime.h>
#include <cuda_bf16.h>

#define BB 16384
#define TT 64

// Ping-pong layer buffers: [B][T][64] (fwd in [0:32), bwd in [32:64))
__device__ float g_buf0[BB * TT * 64];
__device__ float g_buf1[BB * TT * 64];

__device__ __forceinline__ float sigf(float x) {
    return __fdividef(1.0f, 1.0f + __expf(-x));
}
__device__ __forceinline__ float tanh_fast(float x) {
    float e = __expf(-2.0f * x);
    return __fdividef(1.0f - e, 1.0f + e);
}

__device__ __forceinline__ void mma16816(float* c, const unsigned* a,
                                         unsigned b0, unsigned b1) {
    asm volatile(
        "mma.sync.aligned.m16n8k16.row.col.f32.bf16.bf16.f32 "
        "{%0,%1,%2,%3}, {%4,%5,%6,%7}, {%8,%9}, {%0,%1,%2,%3};"
        : "+f"(c[0]), "+f"(c[1]), "+f"(c[2]), "+f"(c[3])
        : "r"(a[0]), "r"(a[1]), "r"(a[2]), "r"(a[3]), "r"(b0), "r"(b1));
}
__device__ __forceinline__ void ldsm4(unsigned* r, unsigned addr) {
    asm volatile(
        "ldmatrix.sync.aligned.m8n8.x4.shared.b16 {%0,%1,%2,%3}, [%4];"
        : "=r"(r[0]), "=r"(r[1]), "=r"(r[2]), "=r"(r[3]) : "r"(addr));
}
__device__ __forceinline__ void ldsm2(unsigned* r, unsigned addr) {
    asm volatile(
        "ldmatrix.sync.aligned.m8n8.x2.shared.b16 {%0,%1}, [%2];"
        : "=r"(r[0]), "=r"(r[1]) : "r"(addr));
}
// 3-pass Markidis accumulate: c += Ahi*Bhi + Ahi*Blo + Alo*Bhi
__device__ __forceinline__ void mma3(float* c, const unsigned* ah, const unsigned* al,
                                     unsigned bh0, unsigned bh1,
                                     unsigned bl0, unsigned bl1) {
    mma16816(c, ah, bh0, bh1);
    mma16816(c, ah, bl0, bl1);
    mma16816(c, al, bh0, bh1);
}
// Split two floats into packed bf16x2 hi / lo residual pairs.
__device__ __forceinline__ void split2(float a, float b, unsigned& hi, unsigned& lo) {
    __nv_bfloat16 ah = __float2bfloat16(a), bh = __float2bfloat16(b);
    __nv_bfloat16 al = __float2bfloat16(a - __bfloat162float(ah));
    __nv_bfloat16 bl = __float2bfloat16(b - __bfloat162float(bh));
    __nv_bfloat162 ph(ah, bh), pl(al, bl);
    hi = *(unsigned*)&ph; lo = *(unsigned*)&pl;
}

#define XELEMS (64 * 72)      // one X buffer (bf16 elems)
#define HELEMS (64 * 40)
#define SMEM_FUSED ((2*XELEMS*2 + 2*96*72 + 2*96*40 + 2*HELEMS*2) * 2)  // bytes

// ---------------------------------------------------------------------------
// Layer 0, tensor-core version. Input K=2 -> xg computed with 24 scalar FMAs
// per thread per step (x sequence staged once in smem, stride 132 floats,
// conflict-free). Recurrent K=32 GEMM via the same 3-pass bf16 mma machinery
// as gru_fused. 512 thr = 16 warps = 4 independent mtile groups, per-step
// group-local bar.sync.
// ---------------------------------------------------------------------------
#define XSTRIDE 132
#define SMEM_L0 (64 * XSTRIDE * 4 + 2 * 96 * 40 * 2 + 2 * 2 * HELEMS * 2)

__global__ __launch_bounds__(512, 2) void gru_l0_mma(
    const float* __restrict__ x,
    const float* __restrict__ Wih0, const float* __restrict__ Whh0,
    const float* __restrict__ bih0, const float* __restrict__ bhh0)
{
    float* out = g_buf0;
    const int dir = blockIdx.y;
    const size_t b0 = (size_t)blockIdx.x * 64;

    extern __shared__ __align__(16) char sm_raw[];
    float* Xs = (float*)sm_raw;                         // [64][132]
    __nv_bfloat16* Ush = (__nv_bfloat16*)(Xs + 64 * XSTRIDE);  // [96][40]
    __nv_bfloat16* Usl = Ush + 96 * 40;
    __nv_bfloat16* Hh  = Usl + 96 * 40;                 // [2][64][40]
    __nv_bfloat16* Hl  = Hh + 2 * HELEMS;

    const int tid = threadIdx.x;
    const float* Wi = Wih0 + (size_t)dir * 96 * 2;
    const float* Wh = Whh0 + (size_t)dir * 96 * 32;
    const float* bi = bih0 + dir * 96;
    const float* bh = bhh0 + dir * 96;

    // ---- Stage recurrent weights (split hi/lo) ----
    for (int q = tid; q < 96 * 8; q += 512) {
        const int gr = q >> 3, k4 = (q & 7) << 2;
        float4 v = *(const float4*)&Wh[gr * 32 + k4];
        unsigned h0, l0, h1, l1;
        split2(v.x, v.y, h0, l0);
        split2(v.z, v.w, h1, l1);
        *(unsigned*)&Ush[gr * 40 + k4]     = h0;
        *(unsigned*)&Ush[gr * 40 + k4 + 2] = h1;
        *(unsigned*)&Usl[gr * 40 + k4]     = l0;
        *(unsigned*)&Usl[gr * 40 + k4 + 2] = l1;
    }
    // ---- Stage whole x sequence: x[b0+r][0..127] -> Xs[r][0..127] ----
    for (int q = tid; q < 2048; q += 512) {
        const int r = q >> 5, c4 = (q & 31) << 2;
        float4 v = *(const float4*)(x + (b0 + r) * 128 + c4);
        *(float4*)&Xs[r * XSTRIDE + c4] = v;
    }
    // ---- Zero H ----
    for (int q = tid; q < 2 * HELEMS / 2; q += 512) {
        ((unsigned*)Hh)[q] = 0u;
        ((unsigned*)Hl)[q] = 0u;
    }

    // ---- Thread geometry (identical to gru_fused) ----
    const int wid = tid >> 5, lane = tid & 31;
    const int mtile = wid >> 2;
    const int mrow0 = mtile << 4;
    const int ug  = wid & 3;
    const int u0  = ug << 3;
    const int g   = lane >> 2;
    const int t2  = (lane & 3) << 1;
    const int ub  = u0 + t2;

    // Biases.
    float bias_r[2], bias_z[2], bias_xn[2], bias_hn[2];
#pragma unroll
    for (int c = 0; c < 2; c++) {
        bias_r[c]  = bi[ub + c]      + bh[ub + c];
        bias_z[c]  = bi[32 + ub + c] + bh[32 + ub + c];
        bias_xn[c] = bi[64 + ub + c];
        bias_hn[c] = bh[64 + ub + c];
    }
    // Input weights for this thread's 2 unit-columns (K=2).
    float wxr[2][2], wxz[2][2], wxn[2][2];   // [c][k]
#pragma unroll
    for (int c = 0; c < 2; c++) {
        wxr[c][0] = Wi[(ub + c) * 2 + 0];      wxr[c][1] = Wi[(ub + c) * 2 + 1];
        wxz[c][0] = Wi[(32 + ub + c) * 2 + 0]; wxz[c][1] = Wi[(32 + ub + c) * 2 + 1];
        wxn[c][0] = Wi[(64 + ub + c) * 2 + 0]; wxn[c][1] = Wi[(64 + ub + c) * 2 + 1];
    }

    // ldmatrix addresses for hgate.
    const int a_r = lane & 15, a_k = (lane >> 4) << 3;
    const unsigned hAhi = (unsigned)__cvta_generic_to_shared(&Hh[(mrow0 + a_r) * 40 + a_k]);
    const unsigned hAlo = (unsigned)__cvta_generic_to_shared(&Hl[(mrow0 + a_r) * 40 + a_k]);
    const int b_row = (lane & 7), b_kh = ((lane >> 3) & 1) << 3;
    unsigned uBhi_[3], uBlo_[3];
#pragma unroll
    for (int gt = 0; gt < 3; gt++) {
        const int row = gt * 32 + u0 + b_row;
        uBhi_[gt] = (unsigned)__cvta_generic_to_shared(&Ush[row * 40 + b_kh]);
        uBlo_[gt] = (unsigned)__cvta_generic_to_shared(&Usl[row * 40 + b_kh]);
    }
    const unsigned HBUF = HELEMS * 2;

    __syncthreads();

    float hp[4] = {0.f, 0.f, 0.f, 0.f};
    const int barid = 8 + mtile;
    const float* xsa = Xs + (mrow0 + g) * XSTRIDE;
    const float* xsb = Xs + (mrow0 + g + 8) * XSTRIDE;

    for (int t = 0; t < TT; t++) {
        const int buf = t & 1, nbuf = buf ^ 1;
        const int te = dir ? (TT - 1 - t) : t;

        const float2 xa = *(const float2*)&xsa[te * 2];
        const float2 xb = *(const float2*)&xsb[te * 2];

        // Accumulators: bias + scalar xg (K=2).
        float accr[4], accz[4], accxn[4], acchn[4];
        accr[0] = fmaf(xa.y, wxr[0][1], fmaf(xa.x, wxr[0][0], bias_r[0]));
        accr[1] = fmaf(xa.y, wxr[1][1], fmaf(xa.x, wxr[1][0], bias_r[1]));
        accr[2] = fmaf(xb.y, wxr[0][1], fmaf(xb.x, wxr[0][0], bias_r[0]));
        accr[3] = fmaf(xb.y, wxr[1][1], fmaf(xb.x, wxr[1][0], bias_r[1]));
        accz[0] = fmaf(xa.y, wxz[0][1], fmaf(xa.x, wxz[0][0], bias_z[0]));
        accz[1] = fmaf(xa.y, wxz[1][1], fmaf(xa.x, wxz[1][0], bias_z[1]));
        accz[2] = fmaf(xb.y, wxz[0][1], fmaf(xb.x, wxz[0][0], bias_z[0]));
        accz[3] = fmaf(xb.y, wxz[1][1], fmaf(xb.x, wxz[1][0], bias_z[1]));
        accxn[0] = fmaf(xa.y, wxn[0][1], fmaf(xa.x, wxn[0][0], bias_xn[0]));
        accxn[1] = fmaf(xa.y, wxn[1][1], fmaf(xa.x, wxn[1][0], bias_xn[1]));
        accxn[2] = fmaf(xb.y, wxn[0][1], fmaf(xb.x, wxn[0][0], bias_xn[0]));
        accxn[3] = fmaf(xb.y, wxn[1][1], fmaf(xb.x, wxn[1][0], bias_xn[1]));
        acchn[0] = bias_hn[0]; acchn[1] = bias_hn[1];
        acchn[2] = bias_hn[0]; acchn[3] = bias_hn[1];

        // hgate mma: A = H[buf], K=32 (2 chunks).
        const unsigned hoff = buf * HBUF;
#pragma unroll
        for (int ks = 0; ks < 2; ks++) {
            const unsigned ko = ks * 32;
            unsigned ah[4], al[4], bh2[2], bl2[2];
            ldsm4(ah, hAhi + hoff + ko);
            ldsm4(al, hAlo + hoff + ko);
            ldsm2(bh2, uBhi_[0] + ko); ldsm2(bl2, uBlo_[0] + ko);
            mma3(accr, ah, al, bh2[0], bh2[1], bl2[0], bl2[1]);
            ldsm2(bh2, uBhi_[1] + ko); ldsm2(bl2, uBlo_[1] + ko);
            mma3(accz, ah, al, bh2[0], bh2[1], bl2[0], bl2[1]);
            ldsm2(bh2, uBhi_[2] + ko); ldsm2(bl2, uBlo_[2] + ko);
            mma3(acchn, ah, al, bh2[0], bh2[1], bl2[0], bl2[1]);
        }

        // Activations, h update, stores.
        float hh[4];
#pragma unroll
        for (int q = 0; q < 4; q++) {
            const float r = sigf(accr[q]);
            const float z = sigf(accz[q]);
            const float n = tanh_fast(fmaf(r, acchn[q], accxn[q]));
            hh[q] = fmaf(z, hp[q] - n, n);
            hp[q] = hh[q];
        }
        unsigned hi01, lo01, hi23, lo23;
        split2(hh[0], hh[1], hi01, lo01);
        split2(hh[2], hh[3], hi23, lo23);
        const int hbo = nbuf * HELEMS;
        *(unsigned*)&Hh[hbo + (mrow0 + g) * 40 + ub]     = hi01;
        *(unsigned*)&Hl[hbo + (mrow0 + g) * 40 + ub]     = lo01;
        *(unsigned*)&Hh[hbo + (mrow0 + g + 8) * 40 + ub] = hi23;
        *(unsigned*)&Hl[hbo + (mrow0 + g + 8) * 40 + ub] = lo23;

        float2 o01; o01.x = hh[0]; o01.y = hh[1];
        float2 o23; o23.x = hh[2]; o23.y = hh[3];
        *(float2*)&out[(b0 + mrow0 + g) * 4096 + (size_t)te * 64 + dir * 32 + ub] = o01;
        *(float2*)&out[(b0 + mrow0 + g + 8) * 4096 + (size_t)te * 64 + dir * 32 + ub] = o23;

        asm volatile("bar.sync %0, %1;" :: "r"(barid), "r"(128) : "memory");
    }
}

// ---------------------------------------------------------------------------
// Fused tensor-core GRU layer (layers 1/2). (unchanged from round 9)
// ---------------------------------------------------------------------------
__global__ __launch_bounds__(512, 2) void gru_fused(
    int phase,
    const float* __restrict__ Wih_l,  // [2][96][64] this layer
    const float* __restrict__ Whh_l,  // [2][96][32]
    const float* __restrict__ bih_l,  // [2][96]
    const float* __restrict__ bhh_l)  // [2][96]
{
    const float* in  = phase ? g_buf1 : g_buf0;
    float*       out = phase ? g_buf0 : g_buf1;
    const int dir = blockIdx.y;
    const size_t b0 = (size_t)blockIdx.x * 64;

    extern __shared__ __align__(16) __nv_bfloat16 sm[];
    __nv_bfloat16* Xhi = sm;                      // [2][64][72]
    __nv_bfloat16* Xlo = Xhi + 2 * XELEMS;
    __nv_bfloat16* Wsh = Xlo + 2 * XELEMS;        // [96][72]
    __nv_bfloat16* Wsl = Wsh + 96 * 72;
    __nv_bfloat16* Ush = Wsl + 96 * 72;           // [96][40]
    __nv_bfloat16* Usl = Ush + 96 * 40;
    __nv_bfloat16* Hh  = Usl + 96 * 40;           // [2][64][40]
    __nv_bfloat16* Hl  = Hh + 2 * HELEMS;

    const int tid = threadIdx.x;
    const float* Wi = Wih_l + (size_t)dir * 96 * 64;
    const float* Wh = Whh_l + (size_t)dir * 96 * 32;
    const float* bi = bih_l + dir * 96;
    const float* bh = bhh_l + dir * 96;

    for (int q = tid; q < 96 * 16; q += 512) {
        const int gr = q >> 4, k4 = (q & 15) << 2;
        float4 v = *(const float4*)&Wi[gr * 64 + k4];
        unsigned h0, l0, h1, l1;
        split2(v.x, v.y, h0, l0);
        split2(v.z, v.w, h1, l1);
        *(unsigned*)&Wsh[gr * 72 + k4]     = h0;
        *(unsigned*)&Wsh[gr * 72 + k4 + 2] = h1;
        *(unsigned*)&Wsl[gr * 72 + k4]     = l0;
        *(unsigned*)&Wsl[gr * 72 + k4 + 2] = l1;
    }
    for (int q = tid; q < 96 * 8; q += 512) {
        const int gr = q >> 3, k4 = (q & 7) << 2;
        float4 v = *(const float4*)&Wh[gr * 32 + k4];
        unsigned h0, l0, h1, l1;
        split2(v.x, v.y, h0, l0);
        split2(v.z, v.w, h1, l1);
        *(unsigned*)&Ush[gr * 40 + k4]     = h0;
        *(unsigned*)&Ush[gr * 40 + k4 + 2] = h1;
        *(unsigned*)&Usl[gr * 40 + k4]     = l0;
        *(unsigned*)&Usl[gr * 40 + k4 + 2] = l1;
    }
    for (int q = tid; q < 2 * HELEMS / 2; q += 512) {
        ((unsigned*)Hh)[q] = 0u;
        ((unsigned*)Hl)[q] = 0u;
    }

    const int wid = tid >> 5, lane = tid & 31;
    const int mtile = wid >> 2;
    const int mrow0 = mtile << 4;
    const int ug  = wid & 3;
    const int u0  = ug << 3;
    const int g   = lane >> 2;
    const int t2  = (lane & 3) << 1;

    const int ub = u0 + t2;
    float bias_r[2], bias_z[2], bias_xn[2], bias_hn[2];
#pragma unroll
    for (int c = 0; c < 2; c++) {
        bias_r[c]  = bi[ub + c]      + bh[ub + c];
        bias_z[c]  = bi[32 + ub + c] + bh[32 + ub + c];
        bias_xn[c] = bi[64 + ub + c];
        bias_hn[c] = bh[64 + ub + c];
    }

    const int a_r = lane & 15, a_k = (lane >> 4) << 3;
    const unsigned xAhi = (unsigned)__cvta_generic_to_shared(&Xhi[(mrow0 + a_r) * 72 + a_k]);
    const unsigned xAlo = (unsigned)__cvta_generic_to_shared(&Xlo[(mrow0 + a_r) * 72 + a_k]);
    const unsigned hAhi = (unsigned)__cvta_generic_to_shared(&Hh[(mrow0 + a_r) * 40 + a_k]);
    const unsigned hAlo = (unsigned)__cvta_generic_to_shared(&Hl[(mrow0 + a_r) * 40 + a_k]);
    const int b_row = (lane & 7), b_kh = ((lane >> 3) & 1) << 3;
    unsigned wBhi_[3], wBlo_[3], uBhi_[3], uBlo_[3];
#pragma unroll
    for (int gt = 0; gt < 3; gt++) {
        const int row = gt * 32 + u0 + b_row;
        wBhi_[gt] = (unsigned)__cvta_generic_to_shared(&Wsh[row * 72 + b_kh]);
        wBlo_[gt] = (unsigned)__cvta_generic_to_shared(&Wsl[row * 72 + b_kh]);
        uBhi_[gt] = (unsigned)__cvta_generic_to_shared(&Ush[row * 40 + b_kh]);
        uBlo_[gt] = (unsigned)__cvta_generic_to_shared(&Usl[row * 40 + b_kh]);
    }
    const unsigned XBUF = XELEMS * 2;
    const unsigned HBUF = HELEMS * 2;

    const int gtid = tid & 127;
    const int xr = mrow0 + (gtid >> 3);
    const int xc = (gtid & 7) << 3;
    const float* xrow = in + (b0 + xr) * 4096 + xc;
    __nv_bfloat16* xdh = Xhi + xr * 72 + xc;
    __nv_bfloat16* xdl = Xlo + xr * 72 + xc;
    float4 px[2];

    auto store_x = [&](int nb) {
        uint4 hv, lv;
        split2(px[0].x, px[0].y, hv.x, lv.x);
        split2(px[0].z, px[0].w, hv.y, lv.y);
        split2(px[1].x, px[1].y, hv.z, lv.z);
        split2(px[1].z, px[1].w, hv.w, lv.w);
        *(uint4*)(xdh + nb * XELEMS) = hv;
        *(uint4*)(xdl + nb * XELEMS) = lv;
    };

    {
        const int te0 = dir ? (TT - 1) : 0;
        px[0] = *(const float4*)(xrow + te0 * 64);
        px[1] = *(const float4*)(xrow + te0 * 64 + 4);
        store_x(0);
        const int te1 = dir ? (TT - 2) : 1;
        px[0] = *(const float4*)(xrow + te1 * 64);
        px[1] = *(const float4*)(xrow + te1 * 64 + 4);
    }
    __syncthreads();

    float hp[4] = {0.f, 0.f, 0.f, 0.f};
    const int barid = 8 + mtile;

    for (int t = 0; t < TT; t++) {
        const int buf = t & 1, nbuf = buf ^ 1;
        const int te = dir ? (TT - 1 - t) : t;

        if (t + 1 < TT) {
            store_x(nbuf);
            if (t + 2 < TT) {
                const int te2 = dir ? (TT - 3 - t) : (t + 2);
                px[0] = *(const float4*)(xrow + te2 * 64);
                px[1] = *(const float4*)(xrow + te2 * 64 + 4);
            }
        }

        float accr[4], accz[4], accxn[4], acchn[4];
        accr[0] = bias_r[0];  accr[1] = bias_r[1];
        accr[2] = bias_r[0];  accr[3] = bias_r[1];
        accz[0] = bias_z[0];  accz[1] = bias_z[1];
        accz[2] = bias_z[0];  accz[3] = bias_z[1];
        accxn[0] = bias_xn[0]; accxn[1] = bias_xn[1];
        accxn[2] = bias_xn[0]; accxn[3] = bias_xn[1];
        acchn[0] = bias_hn[0]; acchn[1] = bias_hn[1];
        acchn[2] = bias_hn[0]; acchn[3] = bias_hn[1];

        const unsigned xoff = buf * XBUF;
#pragma unroll
        for (int ks = 0; ks < 4; ks++) {
            const unsigned ko = ks * 32;
            unsigned ah[4], al[4], bh2[2], bl2[2];
            ldsm4(ah, xAhi + xoff + ko);
            ldsm4(al, xAlo + xoff + ko);
            ldsm2(bh2, wBhi_[0] + ko); ldsm2(bl2, wBlo_[0] + ko);
            mma3(accr, ah, al, bh2[0], bh2[1], bl2[0], bl2[1]);
            ldsm2(bh2, wBhi_[1] + ko); ldsm2(bl2, wBlo_[1] + ko);
            mma3(accz, ah, al, bh2[0], bh2[1], bl2[0], bl2[1]);
            ldsm2(bh2, wBhi_[2] + ko); ldsm2(bl2, wBlo_[2] + ko);
            mma3(accxn, ah, al, bh2[0], bh2[1], bl2[0], bl2[1]);
        }

        const unsigned hoff = buf * HBUF;
#pragma unroll
        for (int ks = 0; ks < 2; ks++) {
            const unsigned ko = ks * 32;
            unsigned ah[4], al[4], bh2[2], bl2[2];
            ldsm4(ah, hAhi + hoff + ko);
            ldsm4(al, hAlo + hoff + ko);
            ldsm2(bh2, uBhi_[0] + ko); ldsm2(bl2, uBlo_[0] + ko);
            mma3(accr, ah, al, bh2[0], bh2[1], bl2[0], bl2[1]);
            ldsm2(bh2, uBhi_[1] + ko); ldsm2(bl2, uBlo_[1] + ko);
            mma3(accz, ah, al, bh2[0], bh2[1], bl2[0], bl2[1]);
            ldsm2(bh2, uBhi_[2] + ko); ldsm2(bl2, uBlo_[2] + ko);
            mma3(acchn, ah, al, bh2[0], bh2[1], bl2[0], bl2[1]);
        }

        float hh[4];
#pragma unroll
        for (int q = 0; q < 4; q++) {
            const float r = sigf(accr[q]);
            const float z = sigf(accz[q]);
            const float n = tanh_fast(fmaf(r, acchn[q], accxn[q]));
            hh[q] = fmaf(z, hp[q] - n, n);
            hp[q] = hh[q];
        }
        unsigned hi01, lo01, hi23, lo23;
        split2(hh[0], hh[1], hi01, lo01);
        split2(hh[2], hh[3], hi23, lo23);
        const int hbo = nbuf * HELEMS;
        *(unsigned*)&Hh[hbo + (mrow0 + g) * 40 + ub]     = hi01;
        *(unsigned*)&Hl[hbo + (mrow0 + g) * 40 + ub]     = lo01;
        *(unsigned*)&Hh[hbo + (mrow0 + g + 8) * 40 + ub] = hi23;
        *(unsigned*)&Hl[hbo + (mrow0 + g + 8) * 40 + ub] = lo23;

        float2 o01; o01.x = hh[0]; o01.y = hh[1];
        float2 o23; o23.x = hh[2]; o23.y = hh[3];
        *(float2*)&out[(b0 + mrow0 + g) * 4096 + (size_t)te * 64 + dir * 32 + ub] = o01;
        *(float2*)&out[(b0 + mrow0 + g + 8) * 4096 + (size_t)te * 64 + dir * 32 + ub] = o23;

        asm volatile("bar.sync %0, %1;" :: "r"(barid), "r"(128) : "memory");
    }
}

// ---------------------------------------------------------------------------
// Final FC: y = tanh(out @ Wfc.T + bfc). Warp per row, shuffle reduction.
// ---------------------------------------------------------------------------
__global__ __launch_bounds__(256) void fc_kernel(
    const float* __restrict__ Wfc, const float* __restrict__ bfc,
    float* __restrict__ outp)
{
    const float* in = g_buf0;  // layer 2 output
    const int lane = threadIdx.x & 31;
    const int warp = (blockIdx.x * blockDim.x + threadIdx.x) >> 5;
    const int nwarps = (gridDim.x * blockDim.x) >> 5;

    const float w0a = __ldg(&Wfc[2 * lane]),      w0b = __ldg(&Wfc[2 * lane + 1]);
    const float w1a = __ldg(&Wfc[64 + 2 * lane]), w1b = __ldg(&Wfc[64 + 2 * lane + 1]);
    const float b0 = __ldg(&bfc[0]), b1 = __ldg(&bfc[1]);

    const int nrows = BB * TT;
    for (int row = warp; row < nrows; row += nwarps) {
        float2 xv = *(const float2*)&in[(size_t)row * 64 + 2 * lane];
        float y0 = fmaf(xv.y, w0b, xv.x * w0a);
        float y1 = fmaf(xv.y, w1b, xv.x * w1a);
#pragma unroll
        for (int o = 16; o > 0; o >>= 1) {
            y0 += __shfl_xor_sync(0xFFFFFFFFu, y0, o);
            y1 += __shfl_xor_sync(0xFFFFFFFFu, y1, o);
        }
        if (lane == 0) {
            float2 r;
            r.x = tanh_fast(y0 + b0);
            r.y = tanh_fast(y1 + b1);
            *(float2*)&outp[(size_t)row * 2] = r;
        }
    }
}

// ---------------------------------------------------------------------------
extern "C" void kernel_launch(void* const* d_in, const int* in_sizes, int n_in,
                              void* d_out, int out_size)
{
    const float* x    = (const float*)d_in[0];
    const float* Wih0 = (const float*)d_in[1];
    const float* Whh0 = (const float*)d_in[2];
    const float* bih0 = (const float*)d_in[3];
    const float* bhh0 = (const float*)d_in[4];
    const float* Wih  = (const float*)d_in[5];
    const float* Whh  = (const float*)d_in[6];
    const float* bih  = (const float*)d_in[7];
    const float* bhh  = (const float*)d_in[8];
    const float* Wfc  = (const float*)d_in[9];
    const float* bfc  = (const float*)d_in[10];
    float* out = (float*)d_out;

    cudaFuncSetAttribute(gru_fused, cudaFuncAttributeMaxDynamicSharedMemorySize,
                         SMEM_FUSED);
    cudaFuncSetAttribute(gru_l0_mma, cudaFuncAttributeMaxDynamicSharedMemorySize,
                         SMEM_L0);

    // Layer 0 -> buf0 (tensor-core)
    gru_l0_mma<<<dim3(BB / 64, 2), 512, SMEM_L0>>>(x, Wih0, Whh0, bih0, bhh0);
    // Layer 1: buf0 -> buf1 (fused)
    gru_fused<<<dim3(BB / 64, 2), 512, SMEM_FUSED>>>(0, Wih, Whh, bih, bhh);
    // Layer 2: buf1 -> buf0 (fused)
    gru_fused<<<dim3(BB / 64, 2), 512, SMEM_FUSED>>>(
        1, Wih + 2 * 96 * 64, Whh + 2 * 96 * 32, bih + 2 * 96, bhh + 2 * 96);
    // FC
    fc_kernel<<<2048, 256>>>(Wfc, bfc, out);
}